// round 4
// baseline (speedup 1.0000x reference)
#include <cuda_runtime.h>
#include <cuda_bf16.h>
#include <math.h>

// ---------------------------------------------------------------------------
// Problem constants
//   B=2, S=2048, HID=2048, N_HEADS=16, N_KV=4, HEAD_DIM=256, rows = B*S = 4096
//   Q: [4096,4096]  K,V: [4096,1024]  attn_out: [4096,4096]  out: [4096,2048]
// ---------------------------------------------------------------------------
#define ROWS      4096
#define HID       2048
#define NH        16
#define NKV       4
#define HD        256
#define SQ        2048
#define QCOLS     (NH * HD)    // 4096
#define KCOLS     (NKV * HD)   // 1024

// Scratch (static device globals -- no allocation anywhere)
__device__ float g_Q[(size_t)ROWS * QCOLS];
__device__ float g_K[(size_t)ROWS * KCOLS];
__device__ float g_V[(size_t)ROWS * KCOLS];
__device__ float g_A[(size_t)ROWS * QCOLS];

// ---------------------------------------------------------------------------
// SGEMM: C[M,N] = A[M,K] @ B[K,N], row-major, all dims multiples of 128/8.
// 128x128 block tile, 8x8 per thread, BK=8, double-buffered smem, float4 I/O.
// ---------------------------------------------------------------------------
__global__ __launch_bounds__(256) void sgemm128(
    const float* __restrict__ A, const float* __restrict__ B,
    float* __restrict__ C, int M, int N, int K)
{
    __shared__ float As[2][8][128];
    __shared__ float Bs[2][8][128];

    const int tid = threadIdx.x;
    const int tx = tid & 15;
    const int ty = tid >> 4;
    const int row0 = blockIdx.y * 128;
    const int col0 = blockIdx.x * 128;

    const int a_row = tid >> 1;
    const int a_col = (tid & 1) * 4;
    const int b_row = tid >> 5;
    const int b_col = (tid & 31) * 4;

    const float* Aptr = A + (size_t)(row0 + a_row) * K + a_col;
    const float* Bptr = B + (size_t)b_row * N + col0 + b_col;

    float acc[8][8];
#pragma unroll
    for (int i = 0; i < 8; i++)
#pragma unroll
        for (int j = 0; j < 8; j++) acc[i][j] = 0.f;

    // prime buffer 0
    float4 a_ld = *(const float4*)Aptr;
    float4 b_ld = *(const float4*)Bptr;
    As[0][a_col + 0][a_row] = a_ld.x;
    As[0][a_col + 1][a_row] = a_ld.y;
    As[0][a_col + 2][a_row] = a_ld.z;
    As[0][a_col + 3][a_row] = a_ld.w;
    *(float4*)&Bs[0][b_row][b_col] = b_ld;
    __syncthreads();

    const int nk = K >> 3;
    int cur = 0;
    for (int kt = 0; kt < nk; kt++) {
        if (kt + 1 < nk) {
            a_ld = *(const float4*)(Aptr + (kt + 1) * 8);
            b_ld = *(const float4*)(Bptr + (size_t)(kt + 1) * 8 * N);
        }
#pragma unroll
        for (int k = 0; k < 8; k++) {
            float a[8], bb[8];
            float4 t;
            t = *(const float4*)&As[cur][k][ty * 4];
            a[0] = t.x; a[1] = t.y; a[2] = t.z; a[3] = t.w;
            t = *(const float4*)&As[cur][k][ty * 4 + 64];
            a[4] = t.x; a[5] = t.y; a[6] = t.z; a[7] = t.w;
            t = *(const float4*)&Bs[cur][k][tx * 4];
            bb[0] = t.x; bb[1] = t.y; bb[2] = t.z; bb[3] = t.w;
            t = *(const float4*)&Bs[cur][k][tx * 4 + 64];
            bb[4] = t.x; bb[5] = t.y; bb[6] = t.z; bb[7] = t.w;
#pragma unroll
            for (int i = 0; i < 8; i++)
#pragma unroll
                for (int j = 0; j < 8; j++)
                    acc[i][j] += a[i] * bb[j];
        }
        if (kt + 1 < nk) {
            const int nxt = cur ^ 1;
            As[nxt][a_col + 0][a_row] = a_ld.x;
            As[nxt][a_col + 1][a_row] = a_ld.y;
            As[nxt][a_col + 2][a_row] = a_ld.z;
            As[nxt][a_col + 3][a_row] = a_ld.w;
            *(float4*)&Bs[nxt][b_row][b_col] = b_ld;
            __syncthreads();
            cur = nxt;
        }
    }

#pragma unroll
    for (int ii = 0; ii < 2; ii++) {
#pragma unroll
        for (int i = 0; i < 4; i++) {
            const int r = row0 + ii * 64 + ty * 4 + i;
            float* crow = C + (size_t)r * N + col0;
            float4 w0, w1;
            w0.x = acc[ii * 4 + i][0]; w0.y = acc[ii * 4 + i][1];
            w0.z = acc[ii * 4 + i][2]; w0.w = acc[ii * 4 + i][3];
            w1.x = acc[ii * 4 + i][4]; w1.y = acc[ii * 4 + i][5];
            w1.z = acc[ii * 4 + i][6]; w1.w = acc[ii * 4 + i][7];
            *(float4*)&crow[tx * 4]      = w0;
            *(float4*)&crow[tx * 4 + 64] = w1;
        }
    }
}

// ---------------------------------------------------------------------------
// RoPE, in place. buf: [ROWS][n_heads*256]. One thread per (row, head, i<128).
//   d<128:  out = x1*cos - x2*sin ;  d>=128: out = x2*cos + x1*sin
// ---------------------------------------------------------------------------
__global__ void rope_kernel(float* __restrict__ buf, const int* __restrict__ pos_ids,
                            int n_heads)
{
    const int idx = blockIdx.x * blockDim.x + threadIdx.x;
    const int total = ROWS * 128 * 16;  // upper bound; guard below
    const int tot = ROWS * n_heads * 128;
    (void)total;
    if (idx >= tot) return;

    const int i   = idx & 127;
    const int t2  = idx >> 7;
    const int h   = t2 % n_heads;
    const int row = t2 / n_heads;

    const float pos = (float)pos_ids[row];
    const float inv_freq = (float)exp(-((double)(2 * i) / 256.0) * log(10000.0));
    const float ang = pos * inv_freq;
    float s, c;
    sincosf(ang, &s, &c);

    const int stride = n_heads * HD;
    float* p = buf + (size_t)row * stride + h * HD;
    const float x1 = p[i];
    const float x2 = p[i + 128];
    p[i]       = x1 * c - x2 * s;
    p[i + 128] = x2 * c + x1 * s;
}

// ---------------------------------------------------------------------------
// Flash attention (causal, fp32). Grid: (S/64, NH, B). Block: 256 threads.
// Br = Bc = 64, full head dim 256 staged in smem. GQA: kv head = h >> 2.
// ---------------------------------------------------------------------------
#define LDT 260   // padded row stride (floats) for Q/K/V tiles
#define LDP 68    // padded row stride for score tile

#define FLASH_SMEM_FLOATS (3 * 64 * LDT + 64 * LDP + 3 * 64)
#define FLASH_SMEM_BYTES  (FLASH_SMEM_FLOATS * 4)

__global__ __launch_bounds__(256) void flash_kernel(
    const float* __restrict__ Q, const float* __restrict__ K,
    const float* __restrict__ V, float* __restrict__ O)
{
    extern __shared__ float sm[];
    float* Qs  = sm;                    // 64 x LDT
    float* Ks  = Qs + 64 * LDT;         // 64 x LDT
    float* Vs  = Ks + 64 * LDT;         // 64 x LDT
    float* Ps  = Vs + 64 * LDT;         // 64 x LDP
    float* m_s = Ps + 64 * LDP;         // 64
    float* l_s = m_s + 64;              // 64
    float* c_s = l_s + 64;              // 64

    const int tid = threadIdx.x;
    const int tx = tid & 15;
    const int ty = tid >> 4;
    const int qt = blockIdx.x;
    const int h  = blockIdx.y;
    const int b  = blockIdx.z;
    const int kvh = h >> 2;             // repeat_kv quirk: head h uses kv h/4
    const int qrow0 = qt * 64;

    // Load Q tile (64 x 256) -- coalesced float4
    for (int idx = tid; idx < 64 * 64; idx += 256) {
        const int r = idx >> 6, d4 = idx & 63;
        *(float4*)&Qs[r * LDT + d4 * 4] =
            *(const float4*)&Q[(size_t)(b * SQ + qrow0 + r) * QCOLS + h * HD + d4 * 4];
    }
    if (tid < 64) { m_s[tid] = -1e30f; l_s[tid] = 0.f; }

    float o_acc[4][16];
#pragma unroll
    for (int i = 0; i < 4; i++)
#pragma unroll
        for (int d = 0; d < 16; d++) o_acc[i][d] = 0.f;
    __syncthreads();

    for (int kt = 0; kt <= qt; kt++) {
        // Load K, V tiles
        for (int idx = tid; idx < 64 * 64; idx += 256) {
            const int r = idx >> 6, d4 = idx & 63;
            const size_t g = (size_t)(b * SQ + kt * 64 + r) * KCOLS + kvh * HD + d4 * 4;
            *(float4*)&Ks[r * LDT + d4 * 4] = *(const float4*)&K[g];
            *(float4*)&Vs[r * LDT + d4 * 4] = *(const float4*)&V[g];
        }
        __syncthreads();

        // S = Q K^T : 4x4 micro-tile per thread (rows ty+16i, cols tx+16j)
        float acc[4][4];
#pragma unroll
        for (int i = 0; i < 4; i++)
#pragma unroll
            for (int j = 0; j < 4; j++) acc[i][j] = 0.f;

        for (int d4 = 0; d4 < 64; d4++) {
            float4 kf[4];
#pragma unroll
            for (int j = 0; j < 4; j++)
                kf[j] = *(const float4*)&Ks[(tx + 16 * j) * LDT + d4 * 4];
#pragma unroll
            for (int i = 0; i < 4; i++) {
                const float4 qf = *(const float4*)&Qs[(ty + 16 * i) * LDT + d4 * 4];
#pragma unroll
                for (int j = 0; j < 4; j++)
                    acc[i][j] += qf.x * kf[j].x + qf.y * kf[j].y +
                                 qf.z * kf[j].z + qf.w * kf[j].w;
            }
        }

        // scale + causal mask, write score tile
        const bool diag = (kt == qt);
#pragma unroll
        for (int i = 0; i < 4; i++) {
#pragma unroll
            for (int j = 0; j < 4; j++) {
                const int r = ty + 16 * i, c = tx + 16 * j;
                float v = acc[i][j] * 0.0625f;   // 1/sqrt(256)
                if (diag && c > r) v = -1e30f;
                Ps[r * LDP + c] = v;
            }
        }
        __syncthreads();

        // Online softmax: 4 threads per row (consecutive lanes -> quad shfl)
        {
            const int r = tid >> 2, sub = tid & 3;
            float* prow = Ps + r * LDP + sub * 16;
            float mloc = prow[0];
#pragma unroll
            for (int c = 1; c < 16; c++) mloc = fmaxf(mloc, prow[c]);
            mloc = fmaxf(mloc, __shfl_xor_sync(0xffffffffu, mloc, 1));
            mloc = fmaxf(mloc, __shfl_xor_sync(0xffffffffu, mloc, 2));
            const float mprev = m_s[r];
            const float mnew = fmaxf(mprev, mloc);
            float lloc = 0.f;
#pragma unroll
            for (int c = 0; c < 16; c++) {
                const float e = __expf(prow[c] - mnew);
                prow[c] = e;
                lloc += e;
            }
            lloc += __shfl_xor_sync(0xffffffffu, lloc, 1);
            lloc += __shfl_xor_sync(0xffffffffu, lloc, 2);
            const float corr = __expf(mprev - mnew);
            if (sub == 0) {
                m_s[r] = mnew;
                l_s[r] = l_s[r] * corr + lloc;
                c_s[r] = corr;
            }
        }
        __syncthreads();

        // Rescale accumulators, then O += P V  (rows ty+16i, dims tx*16..+15)
#pragma unroll
        for (int i = 0; i < 4; i++) {
            const float cf = c_s[ty + 16 * i];
#pragma unroll
            for (int d = 0; d < 16; d++) o_acc[i][d] *= cf;
        }
        for (int kk = 0; kk < 64; kk++) {
            float4 v4[4];
#pragma unroll
            for (int j = 0; j < 4; j++)
                v4[j] = *(const float4*)&Vs[kk * LDT + tx * 16 + j * 4];
#pragma unroll
            for (int i = 0; i < 4; i++) {
                const float p = Ps[(ty + 16 * i) * LDP + kk];
#pragma unroll
                for (int j = 0; j < 4; j++) {
                    o_acc[i][j * 4 + 0] += p * v4[j].x;
                    o_acc[i][j * 4 + 1] += p * v4[j].y;
                    o_acc[i][j * 4 + 2] += p * v4[j].z;
                    o_acc[i][j * 4 + 3] += p * v4[j].w;
                }
            }
        }
        __syncthreads();
    }

    // Final normalize + store (layout [b, s, h, d] flattened = [4096, 4096])
#pragma unroll
    for (int i = 0; i < 4; i++) {
        const int r = ty + 16 * i;
        const float inv = 1.0f / l_s[r];
        float* dst = O + (size_t)(b * SQ + qrow0 + r) * QCOLS + h * HD + tx * 16;
#pragma unroll
        for (int j = 0; j < 4; j++) {
            float4 w;
            w.x = o_acc[i][j * 4 + 0] * inv;
            w.y = o_acc[i][j * 4 + 1] * inv;
            w.z = o_acc[i][j * 4 + 2] * inv;
            w.w = o_acc[i][j * 4 + 3] * inv;
            *(float4*)&dst[j * 4] = w;
        }
    }
}

// ---------------------------------------------------------------------------
// Launch
// inputs (metadata order): hidden_states, attention_mask, position_ids,
//                          Wq, Wk, Wv, Wo
// ---------------------------------------------------------------------------
extern "C" void kernel_launch(void* const* d_in, const int* in_sizes, int n_in,
                              void* d_out, int out_size)
{
    const float* X   = (const float*)d_in[0];
    // d_in[1] = attention_mask (pure causal; handled analytically)
    const int*   pos = (const int*)d_in[2];
    const float* Wq  = (const float*)d_in[3];
    const float* Wk  = (const float*)d_in[4];
    const float* Wv  = (const float*)d_in[5];
    const float* Wo  = (const float*)d_in[6];
    float* out = (float*)d_out;

    float *Qb, *Kb, *Vb, *Ab;
    cudaGetSymbolAddress((void**)&Qb, g_Q);
    cudaGetSymbolAddress((void**)&Kb, g_K);
    cudaGetSymbolAddress((void**)&Vb, g_V);
    cudaGetSymbolAddress((void**)&Ab, g_A);

    const dim3 blk(256);

    // QKV projections
    sgemm128<<<dim3(QCOLS / 128, ROWS / 128), blk>>>(X, Wq, Qb, ROWS, QCOLS, HID);
    sgemm128<<<dim3(KCOLS / 128, ROWS / 128), blk>>>(X, Wk, Kb, ROWS, KCOLS, HID);
    sgemm128<<<dim3(KCOLS / 128, ROWS / 128), blk>>>(X, Wv, Vb, ROWS, KCOLS, HID);

    // RoPE on Q (16 heads) and K (4 heads)
    rope_kernel<<<(ROWS * NH  * 128 + 255) / 256, 256>>>(Qb, pos, NH);
    rope_kernel<<<(ROWS * NKV * 128 + 255) / 256, 256>>>(Kb, pos, NKV);

    // Causal flash attention
    cudaFuncSetAttribute(flash_kernel, cudaFuncAttributeMaxDynamicSharedMemorySize,
                         FLASH_SMEM_BYTES);
    flash_kernel<<<dim3(SQ / 64, NH, 2), blk, FLASH_SMEM_BYTES>>>(Qb, Kb, Vb, Ab);

    // Output projection
    sgemm128<<<dim3(HID / 128, ROWS / 128), blk>>>(Ab, Wo, out, ROWS, HID, QCOLS);
}

// round 6
// speedup vs baseline: 2.2004x; 2.2004x over previous
#include <cuda_runtime.h>
#include <cuda_bf16.h>
#include <math.h>
#include <stdint.h>

// ---------------------------------------------------------------------------
// Problem constants
//   B=2, S=2048, HID=2048, N_HEADS=16, N_KV=4, HEAD_DIM=256, rows = B*S = 4096
// ---------------------------------------------------------------------------
#define ROWS      4096
#define HID       2048
#define NH        16
#define NKV       4
#define HD        256
#define SQ        2048
#define QCOLS     (NH * HD)    // 4096
#define KCOLS     (NKV * HD)   // 1024

// Scratch (static device globals -- no allocation anywhere)
__device__ float g_Q[(size_t)ROWS * QCOLS];
__device__ float g_K[(size_t)ROWS * KCOLS];
__device__ float g_V[(size_t)ROWS * KCOLS];
__device__ float g_A[(size_t)ROWS * QCOLS];

// ---------------------------------------------------------------------------
// TF32 helpers
// ---------------------------------------------------------------------------
__device__ __forceinline__ float tf32r(float x) {
    float y;
    asm("cvt.rna.tf32.f32 %0, %1;" : "=f"(y) : "f"(x));
    return y;
}

#define MMA_TF32(d, a, b)                                                      \
    asm volatile(                                                              \
        "mma.sync.aligned.m16n8k8.row.col.f32.tf32.tf32.f32 "                  \
        "{%0,%1,%2,%3},{%4,%5,%6,%7},{%8,%9},{%0,%1,%2,%3};"                   \
        : "+f"((d)[0]), "+f"((d)[1]), "+f"((d)[2]), "+f"((d)[3])               \
        : "r"((a)[0]), "r"((a)[1]), "r"((a)[2]), "r"((a)[3]),                  \
          "r"((b)[0]), "r"((b)[1]))

// ---------------------------------------------------------------------------
// TF32 tensor-core GEMM: C[M,N] = A[M,K] @ B[K,N], row-major.
// 128x128 block tile, BK=16, 256 threads = 8 warps (2x4), warp tile 64x32.
// A smem: [m][k] with LDK=20 (conflict-free frag loads).
// B smem: [k][n] with LDN=136 (conflict-free frag loads).
// Double-buffered, register-prefetched. TF32 rounding at smem store.
// ---------------------------------------------------------------------------
#define LDK 20
#define LDN 136

__global__ __launch_bounds__(256) void gemm_tf32(
    const float* __restrict__ A, const float* __restrict__ B,
    float* __restrict__ C, int M, int N, int K)
{
    __shared__ __align__(16) float As[2][128][LDK];
    __shared__ __align__(16) float Bs[2][16][LDN];

    const int tid  = threadIdx.x;
    const int wid  = tid >> 5;
    const int lane = tid & 31;
    const int g    = lane >> 2;     // 0..7
    const int tg   = lane & 3;      // 0..3
    const int wm   = (wid & 1) * 64;
    const int wn   = (wid >> 1) * 32;
    const int row0 = blockIdx.y * 128;
    const int col0 = blockIdx.x * 128;

    float c[4][4][4];
#pragma unroll
    for (int mi = 0; mi < 4; mi++)
#pragma unroll
        for (int ni = 0; ni < 4; ni++)
#pragma unroll
            for (int e = 0; e < 4; e++) c[mi][ni][e] = 0.f;

    // ---- global load mappings ----
    // A tile: 128 rows x 16 k. idx in {tid, tid+256}: row = idx>>2, quad = idx&3.
    const int a_r  = tid >> 2;          // 0..63 (second load: +64)
    const int a_kq = (tid & 3) * 4;     // 0,4,8,12
    // B tile: 16 k x 128 n. idx in {tid, tid+256}: k = idx>>5, nq = idx&31.
    const int b_k  = tid >> 5;          // 0..7 (second load: +8)
    const int b_nq = (tid & 31) * 4;

    const float* Ap0 = A + (size_t)(row0 + a_r)      * K + a_kq;
    const float* Ap1 = A + (size_t)(row0 + a_r + 64) * K + a_kq;
    const float* Bp0 = B + (size_t)b_k       * N + col0 + b_nq;
    const float* Bp1 = B + (size_t)(b_k + 8) * N + col0 + b_nq;

    float4 pa0, pa1, pb0, pb1;

    // prime buffer 0
    pa0 = *(const float4*)Ap0;
    pa1 = *(const float4*)Ap1;
    pb0 = *(const float4*)Bp0;
    pb1 = *(const float4*)Bp1;
    {
        float4 w;
        w.x = tf32r(pa0.x); w.y = tf32r(pa0.y); w.z = tf32r(pa0.z); w.w = tf32r(pa0.w);
        *(float4*)&As[0][a_r][a_kq] = w;
        w.x = tf32r(pa1.x); w.y = tf32r(pa1.y); w.z = tf32r(pa1.z); w.w = tf32r(pa1.w);
        *(float4*)&As[0][a_r + 64][a_kq] = w;
        w.x = tf32r(pb0.x); w.y = tf32r(pb0.y); w.z = tf32r(pb0.z); w.w = tf32r(pb0.w);
        *(float4*)&Bs[0][b_k][b_nq] = w;
        w.x = tf32r(pb1.x); w.y = tf32r(pb1.y); w.z = tf32r(pb1.z); w.w = tf32r(pb1.w);
        *(float4*)&Bs[0][b_k + 8][b_nq] = w;
    }
    __syncthreads();

    const int nk = K >> 4;
    int cur = 0;
    for (int kt = 0; kt < nk; kt++) {
        if (kt + 1 < nk) {
            const size_t ko = (size_t)(kt + 1) * 16;
            pa0 = *(const float4*)(Ap0 + ko);
            pa1 = *(const float4*)(Ap1 + ko);
            pb0 = *(const float4*)(Bp0 + ko * N);
            pb1 = *(const float4*)(Bp1 + ko * N);
        }

#pragma unroll
        for (int s = 0; s < 2; s++) {
            const int ks = s * 8;
            uint32_t af[4][4], bf[4][2];
#pragma unroll
            for (int mi = 0; mi < 4; mi++) {
                const int m = wm + mi * 16 + g;
                af[mi][0] = __float_as_uint(As[cur][m][ks + tg]);
                af[mi][1] = __float_as_uint(As[cur][m + 8][ks + tg]);
                af[mi][2] = __float_as_uint(As[cur][m][ks + tg + 4]);
                af[mi][3] = __float_as_uint(As[cur][m + 8][ks + tg + 4]);
            }
#pragma unroll
            for (int ni = 0; ni < 4; ni++) {
                const int n = wn + ni * 8 + g;
                bf[ni][0] = __float_as_uint(Bs[cur][ks + tg][n]);
                bf[ni][1] = __float_as_uint(Bs[cur][ks + tg + 4][n]);
            }
#pragma unroll
            for (int mi = 0; mi < 4; mi++)
#pragma unroll
                for (int ni = 0; ni < 4; ni++)
                    MMA_TF32(c[mi][ni], af[mi], bf[ni]);
        }

        if (kt + 1 < nk) {
            const int nxt = cur ^ 1;
            float4 w;
            w.x = tf32r(pa0.x); w.y = tf32r(pa0.y); w.z = tf32r(pa0.z); w.w = tf32r(pa0.w);
            *(float4*)&As[nxt][a_r][a_kq] = w;
            w.x = tf32r(pa1.x); w.y = tf32r(pa1.y); w.z = tf32r(pa1.z); w.w = tf32r(pa1.w);
            *(float4*)&As[nxt][a_r + 64][a_kq] = w;
            w.x = tf32r(pb0.x); w.y = tf32r(pb0.y); w.z = tf32r(pb0.z); w.w = tf32r(pb0.w);
            *(float4*)&Bs[nxt][b_k][b_nq] = w;
            w.x = tf32r(pb1.x); w.y = tf32r(pb1.y); w.z = tf32r(pb1.z); w.w = tf32r(pb1.w);
            *(float4*)&Bs[nxt][b_k + 8][b_nq] = w;
            __syncthreads();
            cur = nxt;
        }
    }

    // Epilogue: C fragment c0:(g, 2tg) c1:(g, 2tg+1) c2:(g+8, 2tg) c3:(g+8, 2tg+1)
#pragma unroll
    for (int mi = 0; mi < 4; mi++) {
#pragma unroll
        for (int ni = 0; ni < 4; ni++) {
            const int r  = row0 + wm + mi * 16 + g;
            const int cc = col0 + wn + ni * 8 + tg * 2;
            *(float2*)&C[(size_t)r * N + cc] =
                make_float2(c[mi][ni][0], c[mi][ni][1]);
            *(float2*)&C[(size_t)(r + 8) * N + cc] =
                make_float2(c[mi][ni][2], c[mi][ni][3]);
        }
    }
}

// ---------------------------------------------------------------------------
// RoPE, in place. buf: [ROWS][n_heads*256]. One thread per (row, head, i<128).
// ---------------------------------------------------------------------------
__global__ void rope_kernel(float* __restrict__ buf, const int* __restrict__ pos_ids,
                            int n_heads)
{
    const int idx = blockIdx.x * blockDim.x + threadIdx.x;
    const int tot = ROWS * n_heads * 128;
    if (idx >= tot) return;

    const int i   = idx & 127;
    const int t2  = idx >> 7;
    const int h   = t2 % n_heads;
    const int row = t2 / n_heads;

    const float pos = (float)pos_ids[row];
    const float inv_freq = (float)exp(-((double)(2 * i) / 256.0) * log(10000.0));
    const float ang = pos * inv_freq;
    float s, c;
    sincosf(ang, &s, &c);

    const int stride = n_heads * HD;
    float* p = buf + (size_t)row * stride + h * HD;
    const float x1 = p[i];
    const float x2 = p[i + 128];
    p[i]       = x1 * c - x2 * s;
    p[i + 128] = x2 * c + x1 * s;
}

// ---------------------------------------------------------------------------
// Flash attention (causal, fp32). Grid: (S/64, NH, B). Block: 256 threads.
// Br = Bc = 64, full head dim 256 staged in smem. GQA: kv head = h >> 2.
// ---------------------------------------------------------------------------
#define LDT 260   // padded row stride (floats) for Q/K/V tiles
#define LDP 68    // padded row stride for score tile

#define FLASH_SMEM_FLOATS (3 * 64 * LDT + 64 * LDP + 3 * 64)
#define FLASH_SMEM_BYTES  (FLASH_SMEM_FLOATS * 4)

__global__ __launch_bounds__(256) void flash_kernel(
    const float* __restrict__ Q, const float* __restrict__ K,
    const float* __restrict__ V, float* __restrict__ O)
{
    extern __shared__ float sm[];
    float* Qs  = sm;                    // 64 x LDT
    float* Ks  = Qs + 64 * LDT;         // 64 x LDT
    float* Vs  = Ks + 64 * LDT;         // 64 x LDT
    float* Ps  = Vs + 64 * LDT;         // 64 x LDP
    float* m_s = Ps + 64 * LDP;         // 64
    float* l_s = m_s + 64;              // 64
    float* c_s = l_s + 64;              // 64

    const int tid = threadIdx.x;
    const int tx = tid & 15;
    const int ty = tid >> 4;
    const int qt = blockIdx.x;
    const int h  = blockIdx.y;
    const int b  = blockIdx.z;
    const int kvh = h >> 2;             // repeat_kv quirk: head h uses kv h/4
    const int qrow0 = qt * 64;

    for (int idx = tid; idx < 64 * 64; idx += 256) {
        const int r = idx >> 6, d4 = idx & 63;
        *(float4*)&Qs[r * LDT + d4 * 4] =
            *(const float4*)&Q[(size_t)(b * SQ + qrow0 + r) * QCOLS + h * HD + d4 * 4];
    }
    if (tid < 64) { m_s[tid] = -1e30f; l_s[tid] = 0.f; }

    float o_acc[4][16];
#pragma unroll
    for (int i = 0; i < 4; i++)
#pragma unroll
        for (int d = 0; d < 16; d++) o_acc[i][d] = 0.f;
    __syncthreads();

    for (int kt = 0; kt <= qt; kt++) {
        for (int idx = tid; idx < 64 * 64; idx += 256) {
            const int r = idx >> 6, d4 = idx & 63;
            const size_t gofs = (size_t)(b * SQ + kt * 64 + r) * KCOLS + kvh * HD + d4 * 4;
            *(float4*)&Ks[r * LDT + d4 * 4] = *(const float4*)&K[gofs];
            *(float4*)&Vs[r * LDT + d4 * 4] = *(const float4*)&V[gofs];
        }
        __syncthreads();

        float acc[4][4];
#pragma unroll
        for (int i = 0; i < 4; i++)
#pragma unroll
            for (int j = 0; j < 4; j++) acc[i][j] = 0.f;

        for (int d4 = 0; d4 < 64; d4++) {
            float4 kf[4];
#pragma unroll
            for (int j = 0; j < 4; j++)
                kf[j] = *(const float4*)&Ks[(tx + 16 * j) * LDT + d4 * 4];
#pragma unroll
            for (int i = 0; i < 4; i++) {
                const float4 qf = *(const float4*)&Qs[(ty + 16 * i) * LDT + d4 * 4];
#pragma unroll
                for (int j = 0; j < 4; j++)
                    acc[i][j] += qf.x * kf[j].x + qf.y * kf[j].y +
                                 qf.z * kf[j].z + qf.w * kf[j].w;
            }
        }

        const bool diag = (kt == qt);
#pragma unroll
        for (int i = 0; i < 4; i++) {
#pragma unroll
            for (int j = 0; j < 4; j++) {
                const int r = ty + 16 * i, cc = tx + 16 * j;
                float v = acc[i][j] * 0.0625f;   // 1/sqrt(256)
                if (diag && cc > r) v = -1e30f;
                Ps[r * LDP + cc] = v;
            }
        }
        __syncthreads();

        {
            const int r = tid >> 2, sub = tid & 3;
            float* prow = Ps + r * LDP + sub * 16;
            float mloc = prow[0];
#pragma unroll
            for (int cc = 1; cc < 16; cc++) mloc = fmaxf(mloc, prow[cc]);
            mloc = fmaxf(mloc, __shfl_xor_sync(0xffffffffu, mloc, 1));
            mloc = fmaxf(mloc, __shfl_xor_sync(0xffffffffu, mloc, 2));
            const float mprev = m_s[r];
            const float mnew = fmaxf(mprev, mloc);
            float lloc = 0.f;
#pragma unroll
            for (int cc = 0; cc < 16; cc++) {
                const float e = __expf(prow[cc] - mnew);
                prow[cc] = e;
                lloc += e;
            }
            lloc += __shfl_xor_sync(0xffffffffu, lloc, 1);
            lloc += __shfl_xor_sync(0xffffffffu, lloc, 2);
            const float corr = __expf(mprev - mnew);
            if (sub == 0) {
                m_s[r] = mnew;
                l_s[r] = l_s[r] * corr + lloc;
                c_s[r] = corr;
            }
        }
        __syncthreads();

#pragma unroll
        for (int i = 0; i < 4; i++) {
            const float cf = c_s[ty + 16 * i];
#pragma unroll
            for (int d = 0; d < 16; d++) o_acc[i][d] *= cf;
        }
        for (int kk = 0; kk < 64; kk++) {
            float4 v4[4];
#pragma unroll
            for (int j = 0; j < 4; j++)
                v4[j] = *(const float4*)&Vs[kk * LDT + tx * 16 + j * 4];
#pragma unroll
            for (int i = 0; i < 4; i++) {
                const float p = Ps[(ty + 16 * i) * LDP + kk];
#pragma unroll
                for (int j = 0; j < 4; j++) {
                    o_acc[i][j * 4 + 0] += p * v4[j].x;
                    o_acc[i][j * 4 + 1] += p * v4[j].y;
                    o_acc[i][j * 4 + 2] += p * v4[j].z;
                    o_acc[i][j * 4 + 3] += p * v4[j].w;
                }
            }
        }
        __syncthreads();
    }

#pragma unroll
    for (int i = 0; i < 4; i++) {
        const int r = ty + 16 * i;
        const float inv = 1.0f / l_s[r];
        float* dst = O + (size_t)(b * SQ + qrow0 + r) * QCOLS + h * HD + tx * 16;
#pragma unroll
        for (int j = 0; j < 4; j++) {
            float4 w;
            w.x = o_acc[i][j * 4 + 0] * inv;
            w.y = o_acc[i][j * 4 + 1] * inv;
            w.z = o_acc[i][j * 4 + 2] * inv;
            w.w = o_acc[i][j * 4 + 3] * inv;
            *(float4*)&dst[j * 4] = w;
        }
    }
}

// ---------------------------------------------------------------------------
// Launch
// inputs (metadata order): hidden_states, attention_mask, position_ids,
//                          Wq, Wk, Wv, Wo
// ---------------------------------------------------------------------------
extern "C" void kernel_launch(void* const* d_in, const int* in_sizes, int n_in,
                              void* d_out, int out_size)
{
    const float* X   = (const float*)d_in[0];
    const int*   pos = (const int*)d_in[2];
    const float* Wq  = (const float*)d_in[3];
    const float* Wk  = (const float*)d_in[4];
    const float* Wv  = (const float*)d_in[5];
    const float* Wo  = (const float*)d_in[6];
    float* out = (float*)d_out;

    float *Qb, *Kb, *Vb, *Ab;
    cudaGetSymbolAddress((void**)&Qb, g_Q);
    cudaGetSymbolAddress((void**)&Kb, g_K);
    cudaGetSymbolAddress((void**)&Vb, g_V);
    cudaGetSymbolAddress((void**)&Ab, g_A);

    const dim3 blk(256);

    // QKV projections (TF32 tensor cores)
    gemm_tf32<<<dim3(QCOLS / 128, ROWS / 128), blk>>>(X, Wq, Qb, ROWS, QCOLS, HID);
    gemm_tf32<<<dim3(KCOLS / 128, ROWS / 128), blk>>>(X, Wk, Kb, ROWS, KCOLS, HID);
    gemm_tf32<<<dim3(KCOLS / 128, ROWS / 128), blk>>>(X, Wv, Vb, ROWS, KCOLS, HID);

    // RoPE on Q (16 heads) and K (4 heads)
    rope_kernel<<<(ROWS * NH  * 128 + 255) / 256, 256>>>(Qb, pos, NH);
    rope_kernel<<<(ROWS * NKV * 128 + 255) / 256, 256>>>(Kb, pos, NKV);

    // Causal flash attention (fp32)
    cudaFuncSetAttribute(flash_kernel, cudaFuncAttributeMaxDynamicSharedMemorySize,
                         FLASH_SMEM_BYTES);
    flash_kernel<<<dim3(SQ / 64, NH, 2), blk, FLASH_SMEM_BYTES>>>(Qb, Kb, Vb, Ab);

    // Output projection (TF32 tensor cores)
    gemm_tf32<<<dim3(HID / 128, ROWS / 128), blk>>>(Ab, Wo, out, ROWS, HID, QCOLS);
}

// round 8
// speedup vs baseline: 8.0034x; 3.6373x over previous
#include <cuda_runtime.h>
#include <cuda_fp16.h>
#include <math.h>
#include <stdint.h>

// ---------------------------------------------------------------------------
// Problem constants: B=2, S=2048, HID=2048, NH=16, NKV=4, HD=256
// ---------------------------------------------------------------------------
#define ROWS      4096
#define HID       2048
#define NH        16
#define NKV       4
#define HD        256
#define SQ        2048
#define QCOLS     (NH * HD)    // 4096
#define KCOLS     (NKV * HD)   // 1024

// Scratch (static device globals -- no allocation anywhere)
__device__ float  g_Q[(size_t)ROWS * QCOLS];
__device__ float  g_K[(size_t)ROWS * KCOLS];
__device__ float  g_V[(size_t)ROWS * KCOLS];
__device__ float  g_A[(size_t)ROWS * QCOLS];
__device__ __half g_Qh[(size_t)ROWS * QCOLS];                 // scaled + rope'd
__device__ __half g_Kh[(size_t)ROWS * KCOLS];                 // rope'd
__device__ __half g_Vt[(size_t)(2 * NKV) * HD * SQ];          // [b*kvh][dim][key]
__device__ float  g_invfreq[128];

// ---------------------------------------------------------------------------
// Helpers
// ---------------------------------------------------------------------------
__device__ __forceinline__ float tf32r(float x) {
    float y;
    asm("cvt.rna.tf32.f32 %0, %1;" : "=f"(y) : "f"(x));
    return y;
}

// pack two fp32 -> one fp16x2 register (lo = a, hi = b)
__device__ __forceinline__ uint32_t pack_half2(float a, float b) {
    uint32_t r;
    asm("cvt.rn.f16x2.f32 %0, %2, %1;" : "=r"(r) : "f"(a), "f"(b));
    return r;
}

#define MMA_TF32(d, a, b)                                                      \
    asm volatile(                                                              \
        "mma.sync.aligned.m16n8k8.row.col.f32.tf32.tf32.f32 "                  \
        "{%0,%1,%2,%3},{%4,%5,%6,%7},{%8,%9},{%0,%1,%2,%3};"                   \
        : "+f"((d)[0]), "+f"((d)[1]), "+f"((d)[2]), "+f"((d)[3])               \
        : "r"((a)[0]), "r"((a)[1]), "r"((a)[2]), "r"((a)[3]),                  \
          "r"((b)[0]), "r"((b)[1]))

#define MMA_FP16(d, a, b)                                                      \
    asm volatile(                                                              \
        "mma.sync.aligned.m16n8k16.row.col.f32.f16.f16.f32 "                   \
        "{%0,%1,%2,%3},{%4,%5,%6,%7},{%8,%9},{%0,%1,%2,%3};"                   \
        : "+f"((d)[0]), "+f"((d)[1]), "+f"((d)[2]), "+f"((d)[3])               \
        : "r"((a)[0]), "r"((a)[1]), "r"((a)[2]), "r"((a)[3]),                  \
          "r"((b)[0]), "r"((b)[1]))

// ---------------------------------------------------------------------------
// TF32 tensor-core GEMM (proven in R5): C[M,N] = A[M,K] @ B[K,N], row-major.
// ---------------------------------------------------------------------------
#define LDK 20
#define LDN 136

__global__ __launch_bounds__(256) void gemm_tf32(
    const float* __restrict__ A, const float* __restrict__ B,
    float* __restrict__ C, int M, int N, int K)
{
    __shared__ __align__(16) float As[2][128][LDK];
    __shared__ __align__(16) float Bs[2][16][LDN];

    const int tid  = threadIdx.x;
    const int wid  = tid >> 5;
    const int lane = tid & 31;
    const int g    = lane >> 2;
    const int tg   = lane & 3;
    const int wm   = (wid & 1) * 64;
    const int wn   = (wid >> 1) * 32;
    const int row0 = blockIdx.y * 128;
    const int col0 = blockIdx.x * 128;

    float c[4][4][4];
#pragma unroll
    for (int mi = 0; mi < 4; mi++)
#pragma unroll
        for (int ni = 0; ni < 4; ni++)
#pragma unroll
            for (int e = 0; e < 4; e++) c[mi][ni][e] = 0.f;

    const int a_r  = tid >> 2;
    const int a_kq = (tid & 3) * 4;
    const int b_k  = tid >> 5;
    const int b_nq = (tid & 31) * 4;

    const float* Ap0 = A + (size_t)(row0 + a_r)      * K + a_kq;
    const float* Ap1 = A + (size_t)(row0 + a_r + 64) * K + a_kq;
    const float* Bp0 = B + (size_t)b_k       * N + col0 + b_nq;
    const float* Bp1 = B + (size_t)(b_k + 8) * N + col0 + b_nq;

    float4 pa0, pa1, pb0, pb1;
    pa0 = *(const float4*)Ap0;
    pa1 = *(const float4*)Ap1;
    pb0 = *(const float4*)Bp0;
    pb1 = *(const float4*)Bp1;
    {
        float4 w;
        w.x = tf32r(pa0.x); w.y = tf32r(pa0.y); w.z = tf32r(pa0.z); w.w = tf32r(pa0.w);
        *(float4*)&As[0][a_r][a_kq] = w;
        w.x = tf32r(pa1.x); w.y = tf32r(pa1.y); w.z = tf32r(pa1.z); w.w = tf32r(pa1.w);
        *(float4*)&As[0][a_r + 64][a_kq] = w;
        w.x = tf32r(pb0.x); w.y = tf32r(pb0.y); w.z = tf32r(pb0.z); w.w = tf32r(pb0.w);
        *(float4*)&Bs[0][b_k][b_nq] = w;
        w.x = tf32r(pb1.x); w.y = tf32r(pb1.y); w.z = tf32r(pb1.z); w.w = tf32r(pb1.w);
        *(float4*)&Bs[0][b_k + 8][b_nq] = w;
    }
    __syncthreads();

    const int nk = K >> 4;
    int cur = 0;
    for (int kt = 0; kt < nk; kt++) {
        if (kt + 1 < nk) {
            const size_t ko = (size_t)(kt + 1) * 16;
            pa0 = *(const float4*)(Ap0 + ko);
            pa1 = *(const float4*)(Ap1 + ko);
            pb0 = *(const float4*)(Bp0 + ko * N);
            pb1 = *(const float4*)(Bp1 + ko * N);
        }
#pragma unroll
        for (int s = 0; s < 2; s++) {
            const int ks = s * 8;
            uint32_t af[4][4], bf[4][2];
#pragma unroll
            for (int mi = 0; mi < 4; mi++) {
                const int m = wm + mi * 16 + g;
                af[mi][0] = __float_as_uint(As[cur][m][ks + tg]);
                af[mi][1] = __float_as_uint(As[cur][m + 8][ks + tg]);
                af[mi][2] = __float_as_uint(As[cur][m][ks + tg + 4]);
                af[mi][3] = __float_as_uint(As[cur][m + 8][ks + tg + 4]);
            }
#pragma unroll
            for (int ni = 0; ni < 4; ni++) {
                const int n = wn + ni * 8 + g;
                bf[ni][0] = __float_as_uint(Bs[cur][ks + tg][n]);
                bf[ni][1] = __float_as_uint(Bs[cur][ks + tg + 4][n]);
            }
#pragma unroll
            for (int mi = 0; mi < 4; mi++)
#pragma unroll
                for (int ni = 0; ni < 4; ni++)
                    MMA_TF32(c[mi][ni], af[mi], bf[ni]);
        }
        if (kt + 1 < nk) {
            const int nxt = cur ^ 1;
            float4 w;
            w.x = tf32r(pa0.x); w.y = tf32r(pa0.y); w.z = tf32r(pa0.z); w.w = tf32r(pa0.w);
            *(float4*)&As[nxt][a_r][a_kq] = w;
            w.x = tf32r(pa1.x); w.y = tf32r(pa1.y); w.z = tf32r(pa1.z); w.w = tf32r(pa1.w);
            *(float4*)&As[nxt][a_r + 64][a_kq] = w;
            w.x = tf32r(pb0.x); w.y = tf32r(pb0.y); w.z = tf32r(pb0.z); w.w = tf32r(pb0.w);
            *(float4*)&Bs[nxt][b_k][b_nq] = w;
            w.x = tf32r(pb1.x); w.y = tf32r(pb1.y); w.z = tf32r(pb1.z); w.w = tf32r(pb1.w);
            *(float4*)&Bs[nxt][b_k + 8][b_nq] = w;
            __syncthreads();
            cur = nxt;
        }
    }
#pragma unroll
    for (int mi = 0; mi < 4; mi++) {
#pragma unroll
        for (int ni = 0; ni < 4; ni++) {
            const int r  = row0 + wm + mi * 16 + g;
            const int cc = col0 + wn + ni * 8 + tg * 2;
            *(float2*)&C[(size_t)r * N + cc] =
                make_float2(c[mi][ni][0], c[mi][ni][1]);
            *(float2*)&C[(size_t)(r + 8) * N + cc] =
                make_float2(c[mi][ni][2], c[mi][ni][3]);
        }
    }
}

// ---------------------------------------------------------------------------
// inv_freq table: fp64 exp computed ONCE by 128 threads (was the 694us bug)
// ---------------------------------------------------------------------------
__global__ void init_invfreq()
{
    const int i = threadIdx.x;  // 0..127
    g_invfreq[i] = (float)exp(-((double)(2 * i) / 256.0) * log(10000.0));
}

// ---------------------------------------------------------------------------
// RoPE -> fp16. Reads fp32 proj output, writes rope'd __half (scale folded).
// ---------------------------------------------------------------------------
__global__ void rope16(const float* __restrict__ in, __half* __restrict__ out,
                       const int* __restrict__ pos_ids, int n_heads, float scale)
{
    const int idx = blockIdx.x * blockDim.x + threadIdx.x;
    const int tot = ROWS * n_heads * 128;
    if (idx >= tot) return;

    const int i   = idx & 127;
    const int t2  = idx >> 7;
    const int h   = t2 % n_heads;
    const int row = t2 / n_heads;

    const float ang = (float)pos_ids[row] * g_invfreq[i];
    float s, c;
    sincosf(ang, &s, &c);

    const int stride = n_heads * HD;
    const size_t base = (size_t)row * stride + h * HD;
    const float x1 = in[base + i];
    const float x2 = in[base + i + 128];
    out[base + i]       = __float2half_rn((x1 * c - x2 * s) * scale);
    out[base + i + 128] = __float2half_rn((x2 * c + x1 * s) * scale);
}

// ---------------------------------------------------------------------------
// V: fp32 [b*S][kvh*256+d] -> fp16 transposed [b*NKV+kvh][d][s]
// ---------------------------------------------------------------------------
__global__ void vtrans(const float* __restrict__ V, __half* __restrict__ Vt)
{
    const int idx = blockIdx.x * blockDim.x + threadIdx.x;
    if (idx >= 2 * NKV * HD * SQ) return;
    const int s   = idx & (SQ - 1);
    const int d   = (idx >> 11) & (HD - 1);
    const int bk  = idx >> 19;            // 0..7
    const int b   = bk >> 2, kvh = bk & 3;
    const float v = V[((size_t)(b * SQ + s)) * KCOLS + kvh * HD + d];
    Vt[((size_t)bk * HD + d) * SQ + s] = __float2half_rn(v);
}

// ---------------------------------------------------------------------------
// fp16 tensor-core causal flash attention.
// Grid (32, NH, B), 128 threads = 4 warps. Br=64 (16 rows/warp), Bc=64, D=256.
// Q pre-scaled by 1/16. Scores + O accum fp32. GQA: kv head = h>>2.
// ---------------------------------------------------------------------------
#define QK_LDH 264   // halves per row for Qs/Ks (stride 33 x 16B -> conflict-free)
#define VT_LDH 72    // halves per row for Vs (transposed V, stride 4.5 x 16B)
#define FL_SMEM_BYTES ((2 * 64 * QK_LDH + 256 * VT_LDH) * 2)

__global__ __launch_bounds__(128) void flash16(
    const __half* __restrict__ Q, const __half* __restrict__ K,
    const __half* __restrict__ Vt, float* __restrict__ O)
{
    extern __shared__ __half sh[];
    __half* Qs = sh;                       // 64 x QK_LDH
    __half* Ks = Qs + 64 * QK_LDH;         // 64 x QK_LDH
    __half* Vs = Ks + 64 * QK_LDH;         // 256 x VT_LDH  ([dim][key])

    const int tid  = threadIdx.x;
    const int lane = tid & 31;
    const int w    = tid >> 5;
    const int g    = lane >> 2;
    const int tg   = lane & 3;
    const int qt   = 31 - blockIdx.x;      // longest tiles first
    const int h    = blockIdx.y;
    const int b    = blockIdx.z;
    const int kvh  = h >> 2;
    const int qrow0 = qt * 64;
    const int wr   = w * 16;

    // Load Q tile (64 x 256 halves)
    {
        const __half* Qg = Q + (size_t)(b * SQ + qrow0) * QCOLS + h * HD;
#pragma unroll
        for (int it = 0; it < 16; it++) {
            const int idx = tid + it * 128;
            const int r = idx >> 5, c8 = idx & 31;
            *(uint4*)&Qs[r * QK_LDH + c8 * 8] =
                *(const uint4*)&Qg[(size_t)r * QCOLS + c8 * 8];
        }
    }

    float o[32][4];
#pragma unroll
    for (int jd = 0; jd < 32; jd++)
#pragma unroll
        for (int e = 0; e < 4; e++) o[jd][e] = 0.f;
    float m0 = -1e30f, m1 = -1e30f, l0 = 0.f, l1 = 0.f;
    __syncthreads();

    for (int kt = 0; kt <= qt; kt++) {
        // Load K (row-major) and Vt (dim-major) tiles
        {
            const __half* Kg = K + (size_t)(b * SQ + kt * 64) * KCOLS + kvh * HD;
            const __half* Vg = Vt + ((size_t)(b * NKV + kvh) * HD) * SQ + kt * 64;
#pragma unroll
            for (int it = 0; it < 16; it++) {
                const int idx = tid + it * 128;
                const int r = idx >> 5, c8 = idx & 31;
                *(uint4*)&Ks[r * QK_LDH + c8 * 8] =
                    *(const uint4*)&Kg[(size_t)r * KCOLS + c8 * 8];
                const int d = idx >> 3, k8 = idx & 7;
                *(uint4*)&Vs[d * VT_LDH + k8 * 8] =
                    *(const uint4*)&Vg[(size_t)d * SQ + k8 * 8];
            }
        }
        __syncthreads();

        // S = Q K^T (scale already folded into Q)
        float s[8][4];
#pragma unroll
        for (int j = 0; j < 8; j++)
#pragma unroll
            for (int e = 0; e < 4; e++) s[j][e] = 0.f;

#pragma unroll
        for (int kc = 0; kc < 16; kc++) {
            uint32_t a[4];
            a[0] = *(const uint32_t*)&Qs[(wr + g)     * QK_LDH + kc * 16 + 2 * tg];
            a[1] = *(const uint32_t*)&Qs[(wr + g + 8) * QK_LDH + kc * 16 + 2 * tg];
            a[2] = *(const uint32_t*)&Qs[(wr + g)     * QK_LDH + kc * 16 + 2 * tg + 8];
            a[3] = *(const uint32_t*)&Qs[(wr + g + 8) * QK_LDH + kc * 16 + 2 * tg + 8];
#pragma unroll
            for (int j = 0; j < 8; j++) {
                uint32_t bf[2];
                bf[0] = *(const uint32_t*)&Ks[(j * 8 + g) * QK_LDH + kc * 16 + 2 * tg];
                bf[1] = *(const uint32_t*)&Ks[(j * 8 + g) * QK_LDH + kc * 16 + 2 * tg + 8];
                MMA_FP16(s[j], a, bf);
            }
        }

        // Causal mask on the diagonal tile
        if (kt == qt) {
            const int r0 = wr + g, r1 = wr + g + 8;
#pragma unroll
            for (int j = 0; j < 8; j++) {
                const int c0 = j * 8 + 2 * tg, c1 = c0 + 1;
                if (c0 > r0) s[j][0] = -1e30f;
                if (c1 > r0) s[j][1] = -1e30f;
                if (c0 > r1) s[j][2] = -1e30f;
                if (c1 > r1) s[j][3] = -1e30f;
            }
        }

        // Online softmax (quad = 4 lanes sharing rows g / g+8)
        float tm0 = -1e30f, tm1 = -1e30f;
#pragma unroll
        for (int j = 0; j < 8; j++) {
            tm0 = fmaxf(tm0, fmaxf(s[j][0], s[j][1]));
            tm1 = fmaxf(tm1, fmaxf(s[j][2], s[j][3]));
        }
        tm0 = fmaxf(tm0, __shfl_xor_sync(0xffffffffu, tm0, 1));
        tm0 = fmaxf(tm0, __shfl_xor_sync(0xffffffffu, tm0, 2));
        tm1 = fmaxf(tm1, __shfl_xor_sync(0xffffffffu, tm1, 1));
        tm1 = fmaxf(tm1, __shfl_xor_sync(0xffffffffu, tm1, 2));

        const float mn0 = fmaxf(m0, tm0), mn1 = fmaxf(m1, tm1);
        const float cf0 = __expf(m0 - mn0), cf1 = __expf(m1 - mn1);
        m0 = mn0; m1 = mn1;

        uint32_t pf[8][2];
        float ls0 = 0.f, ls1 = 0.f;
#pragma unroll
        for (int j = 0; j < 8; j++) {
            const float p00 = __expf(s[j][0] - m0);
            const float p01 = __expf(s[j][1] - m0);
            const float p10 = __expf(s[j][2] - m1);
            const float p11 = __expf(s[j][3] - m1);
            ls0 += p00 + p01;
            ls1 += p10 + p11;
            pf[j][0] = pack_half2(p00, p01);
            pf[j][1] = pack_half2(p10, p11);
        }
        ls0 += __shfl_xor_sync(0xffffffffu, ls0, 1);
        ls0 += __shfl_xor_sync(0xffffffffu, ls0, 2);
        ls1 += __shfl_xor_sync(0xffffffffu, ls1, 1);
        ls1 += __shfl_xor_sync(0xffffffffu, ls1, 2);
        l0 = l0 * cf0 + ls0;
        l1 = l1 * cf1 + ls1;

        // Rescale O, then O += P V
#pragma unroll
        for (int jd = 0; jd < 32; jd++) {
            o[jd][0] *= cf0; o[jd][1] *= cf0;
            o[jd][2] *= cf1; o[jd][3] *= cf1;
        }
#pragma unroll
        for (int kc = 0; kc < 4; kc++) {
            uint32_t a[4] = { pf[2 * kc][0], pf[2 * kc][1],
                              pf[2 * kc + 1][0], pf[2 * kc + 1][1] };
#pragma unroll
            for (int jd = 0; jd < 32; jd++) {
                uint32_t bf[2];
                bf[0] = *(const uint32_t*)&Vs[(jd * 8 + g) * VT_LDH + kc * 16 + 2 * tg];
                bf[1] = *(const uint32_t*)&Vs[(jd * 8 + g) * VT_LDH + kc * 16 + 2 * tg + 8];
                MMA_FP16(o[jd], a, bf);
            }
        }
        __syncthreads();
    }

    // Normalize + store fp32 to attention-out buffer
    const float inv0 = 1.0f / l0, inv1 = 1.0f / l1;
    const size_t r0 = (size_t)(b * SQ + qrow0 + wr + g) * QCOLS + h * HD;
    const size_t r1 = (size_t)(b * SQ + qrow0 + wr + g + 8) * QCOLS + h * HD;
#pragma unroll
    for (int jd = 0; jd < 32; jd++) {
        const int cc = jd * 8 + 2 * tg;
        *(float2*)&O[r0 + cc] = make_float2(o[jd][0] * inv0, o[jd][1] * inv0);
        *(float2*)&O[r1 + cc] = make_float2(o[jd][2] * inv1, o[jd][3] * inv1);
    }
}

// ---------------------------------------------------------------------------
// Launch. inputs: hidden_states, attention_mask, position_ids, Wq, Wk, Wv, Wo
// ---------------------------------------------------------------------------
extern "C" void kernel_launch(void* const* d_in, const int* in_sizes, int n_in,
                              void* d_out, int out_size)
{
    const float* X   = (const float*)d_in[0];
    const int*   pos = (const int*)d_in[2];
    const float* Wq  = (const float*)d_in[3];
    const float* Wk  = (const float*)d_in[4];
    const float* Wv  = (const float*)d_in[5];
    const float* Wo  = (const float*)d_in[6];
    float* out = (float*)d_out;

    float *Qb, *Kb, *Vb, *Ab;
    __half *Qh, *Kh, *Vth;
    cudaGetSymbolAddress((void**)&Qb, g_Q);
    cudaGetSymbolAddress((void**)&Kb, g_K);
    cudaGetSymbolAddress((void**)&Vb, g_V);
    cudaGetSymbolAddress((void**)&Ab, g_A);
    cudaGetSymbolAddress((void**)&Qh, g_Qh);
    cudaGetSymbolAddress((void**)&Kh, g_Kh);
    cudaGetSymbolAddress((void**)&Vth, g_Vt);

    const dim3 blk(256);

    init_invfreq<<<1, 128>>>();

    // QKV projections (TF32 tensor cores)
    gemm_tf32<<<dim3(QCOLS / 128, ROWS / 128), blk>>>(X, Wq, Qb, ROWS, QCOLS, HID);
    gemm_tf32<<<dim3(KCOLS / 128, ROWS / 128), blk>>>(X, Wk, Kb, ROWS, KCOLS, HID);
    gemm_tf32<<<dim3(KCOLS / 128, ROWS / 128), blk>>>(X, Wv, Vb, ROWS, KCOLS, HID);

    // RoPE -> fp16 (Q gets 1/sqrt(256) folded in); V -> fp16 transposed
    rope16<<<(ROWS * NH  * 128 + 255) / 256, 256>>>(Qb, Qh, pos, NH, 0.0625f);
    rope16<<<(ROWS * NKV * 128 + 255) / 256, 256>>>(Kb, Kh, pos, NKV, 1.0f);
    vtrans<<<(2 * NKV * HD * SQ + 255) / 256, 256>>>(Vb, Vth);

    // fp16 tensor-core causal flash attention
    cudaFuncSetAttribute(flash16, cudaFuncAttributeMaxDynamicSharedMemorySize,
                         FL_SMEM_BYTES);
    flash16<<<dim3(SQ / 64, NH, 2), 128, FL_SMEM_BYTES>>>(Qh, Kh, Vth, Ab);

    // Output projection (TF32 tensor cores)
    gemm_tf32<<<dim3(HID / 128, ROWS / 128), blk>>>(Ab, Wo, out, ROWS, HID, QCOLS);
}

// round 9
// speedup vs baseline: 12.2392x; 1.5292x over previous
#include <cuda_runtime.h>
#include <cuda_fp16.h>
#include <math.h>
#include <stdint.h>

// ---------------------------------------------------------------------------
// Problem constants: B=2, S=2048, HID=2048, NH=16, NKV=4, HD=256
// ---------------------------------------------------------------------------
#define ROWS      4096
#define HID       2048
#define NH        16
#define NKV       4
#define HD        256
#define SQ        2048
#define QCOLS     (NH * HD)    // 4096
#define KCOLS     (NKV * HD)   // 1024

// Scratch (static device globals -- no allocation anywhere)
__device__ float  g_Q[(size_t)ROWS * QCOLS];                  // fp32 Q proj
__device__ float  g_K[(size_t)ROWS * KCOLS];
__device__ float  g_V[(size_t)ROWS * KCOLS];
__device__ __half g_Qh[(size_t)ROWS * QCOLS];                 // rope'd, scaled
__device__ __half g_Kh[(size_t)ROWS * KCOLS];                 // rope'd
__device__ __half g_Vt[(size_t)(2 * NKV) * HD * SQ];          // [b*kvh][dim][key]
__device__ __half g_Ah[(size_t)ROWS * QCOLS];                 // attention out fp16
__device__ __half g_Xh[(size_t)ROWS * HID];                   // hidden fp16
__device__ __half g_WqT[(size_t)QCOLS * HID];                 // [N][K] fp16
__device__ __half g_WkT[(size_t)KCOLS * HID];
__device__ __half g_WvT[(size_t)KCOLS * HID];
__device__ __half g_WoT[(size_t)HID * QCOLS];
__device__ float  g_invfreq[128];

// ---------------------------------------------------------------------------
// Helpers
// ---------------------------------------------------------------------------
__device__ __forceinline__ uint32_t pack_half2(float a, float b) {
    uint32_t r;
    asm("cvt.rn.f16x2.f32 %0, %2, %1;" : "=r"(r) : "f"(a), "f"(b));
    return r;
}

__device__ __forceinline__ void cpa16(uint32_t saddr, const void* gaddr) {
    asm volatile("cp.async.cg.shared.global [%0], [%1], 16;"
                 :: "r"(saddr), "l"(gaddr));
}
#define CP_COMMIT() asm volatile("cp.async.commit_group;")
#define CP_WAIT1()  asm volatile("cp.async.wait_group 1;")

#define MMA_FP16(d, a, b)                                                      \
    asm volatile(                                                              \
        "mma.sync.aligned.m16n8k16.row.col.f32.f16.f16.f32 "                   \
        "{%0,%1,%2,%3},{%4,%5,%6,%7},{%8,%9},{%0,%1,%2,%3};"                   \
        : "+f"((d)[0]), "+f"((d)[1]), "+f"((d)[2]), "+f"((d)[3])               \
        : "r"((a)[0]), "r"((a)[1]), "r"((a)[2]), "r"((a)[3]),                  \
          "r"((b)[0]), "r"((b)[1]))

// ---------------------------------------------------------------------------
// fp16 tensor-core GEMM: C[M,N] = A[M,K] @ Bt[N,K]^T  (both row-major in K).
// 128x128 block tile, BK=32, 256 threads = 8 warps (2x4), warp tile 64x32.
// 3-stage cp.async pipeline. smem rows stride 40 halves (conflict-free).
// ---------------------------------------------------------------------------
#define GLDK   40
#define GSTG   (128 * GLDK)            // halves per matrix per stage (5120)
#define GBOFF  (3 * GSTG)              // Bs base (halves)
#define GEMM_SMEM_BYTES (6 * GSTG * 2) // 61440

__global__ __launch_bounds__(256) void gemm_f16(
    const __half* __restrict__ A, const __half* __restrict__ Bt,
    float* __restrict__ C, int M, int N, int K)
{
    extern __shared__ __half sh[];

    const int tid  = threadIdx.x;
    const int wid  = tid >> 5;
    const int lane = tid & 31;
    const int g    = lane >> 2;
    const int tg   = lane & 3;
    const int wm   = (wid & 1) * 64;
    const int wn   = (wid >> 1) * 32;
    const int row0 = blockIdx.y * 128;
    const int col0 = blockIdx.x * 128;

    // global load mapping: 4 x 16B chunks/row, 512 chunks/tile, 2 per thread
    const int r0  = tid >> 2;          // 0..63  (second chunk: +64)
    const int kc0 = (tid & 3) * 8;     // halves 0,8,16,24

    const __half* Ag0 = A  + (size_t)(row0 + r0)      * K + kc0;
    const __half* Ag1 = A  + (size_t)(row0 + r0 + 64) * K + kc0;
    const __half* Bg0 = Bt + (size_t)(col0 + r0)      * K + kc0;
    const __half* Bg1 = Bt + (size_t)(col0 + r0 + 64) * K + kc0;

    const uint32_t sbase = (uint32_t)__cvta_generic_to_shared(sh);
    const uint32_t aoff  = (uint32_t)(r0 * GLDK + kc0) * 2;
    const uint32_t rstep = 64 * GLDK * 2;

    float acc[4][4][4];
#pragma unroll
    for (int mi = 0; mi < 4; mi++)
#pragma unroll
        for (int ni = 0; ni < 4; ni++)
#pragma unroll
            for (int e = 0; e < 4; e++) acc[mi][ni][e] = 0.f;

    const int nk = K >> 5;             // BK = 32

    // prologue: stages 0, 1
#pragma unroll
    for (int p = 0; p < 2; p++) {
        const uint32_t sa = sbase + (uint32_t)(p * GSTG) * 2 + aoff;
        const uint32_t sb = sbase + (uint32_t)((GBOFF + p * GSTG)) * 2 + aoff;
        const size_t ko = (size_t)p * 32;
        cpa16(sa,         Ag0 + ko);
        cpa16(sa + rstep, Ag1 + ko);
        cpa16(sb,         Bg0 + ko);
        cpa16(sb + rstep, Bg1 + ko);
        CP_COMMIT();
    }

    for (int kt = 0; kt < nk; kt++) {
        CP_WAIT1();
        __syncthreads();

        // prefetch stage kt+2
        if (kt + 2 < nk) {
            const int st2 = (kt + 2) % 3;
            const uint32_t sa = sbase + (uint32_t)(st2 * GSTG) * 2 + aoff;
            const uint32_t sb = sbase + (uint32_t)((GBOFF + st2 * GSTG)) * 2 + aoff;
            const size_t ko = (size_t)(kt + 2) * 32;
            cpa16(sa,         Ag0 + ko);
            cpa16(sa + rstep, Ag1 + ko);
            cpa16(sb,         Bg0 + ko);
            cpa16(sb + rstep, Bg1 + ko);
        }
        CP_COMMIT();

        // compute stage kt%3
        const __half* Asl = sh + (kt % 3) * GSTG;
        const __half* Bsl = sh + GBOFF + (kt % 3) * GSTG;
#pragma unroll
        for (int kc = 0; kc < 2; kc++) {
            uint32_t af[4][4], bf[4][2];
#pragma unroll
            for (int mi = 0; mi < 4; mi++) {
                const int m = wm + mi * 16 + g;
                af[mi][0] = *(const uint32_t*)&Asl[m * GLDK + kc * 16 + 2 * tg];
                af[mi][1] = *(const uint32_t*)&Asl[(m + 8) * GLDK + kc * 16 + 2 * tg];
                af[mi][2] = *(const uint32_t*)&Asl[m * GLDK + kc * 16 + 2 * tg + 8];
                af[mi][3] = *(const uint32_t*)&Asl[(m + 8) * GLDK + kc * 16 + 2 * tg + 8];
            }
#pragma unroll
            for (int ni = 0; ni < 4; ni++) {
                const int n = wn + ni * 8 + g;
                bf[ni][0] = *(const uint32_t*)&Bsl[n * GLDK + kc * 16 + 2 * tg];
                bf[ni][1] = *(const uint32_t*)&Bsl[n * GLDK + kc * 16 + 2 * tg + 8];
            }
#pragma unroll
            for (int mi = 0; mi < 4; mi++)
#pragma unroll
                for (int ni = 0; ni < 4; ni++)
                    MMA_FP16(acc[mi][ni], af[mi], bf[ni]);
        }
        __syncthreads();
    }

    // Epilogue: frag element mapping (row g: c0,c1 @ cols 2tg,2tg+1; row g+8: c2,c3)
#pragma unroll
    for (int mi = 0; mi < 4; mi++) {
#pragma unroll
        for (int ni = 0; ni < 4; ni++) {
            const int r  = row0 + wm + mi * 16 + g;
            const int cc = col0 + wn + ni * 8 + tg * 2;
            *(float2*)&C[(size_t)r * N + cc] =
                make_float2(acc[mi][ni][0], acc[mi][ni][1]);
            *(float2*)&C[(size_t)(r + 8) * N + cc] =
                make_float2(acc[mi][ni][2], acc[mi][ni][3]);
        }
    }
}

// ---------------------------------------------------------------------------
// fp32 -> fp16 (vectorized), n multiple of 4
// ---------------------------------------------------------------------------
__global__ void f2h(const float* __restrict__ in, __half* __restrict__ out, int n)
{
    const int i = blockIdx.x * blockDim.x + threadIdx.x;
    if (i * 4 >= n) return;
    const float4 v = ((const float4*)in)[i];
    uint2 h;
    h.x = pack_half2(v.x, v.y);
    h.y = pack_half2(v.z, v.w);
    ((uint2*)out)[i] = h;
}

// ---------------------------------------------------------------------------
// Weight transpose+convert: W[K][N] fp32 -> Wt[N][K] fp16. 32x32 smem tiles.
// Grid (N/32, K/32), block (32, 8).
// ---------------------------------------------------------------------------
__global__ void wtrans(const float* __restrict__ W, __half* __restrict__ Wt,
                       int K, int N)
{
    __shared__ float tile[32][33];
    const int x = threadIdx.x, y = threadIdx.y;
    const int n0 = blockIdx.x * 32, k0 = blockIdx.y * 32;
#pragma unroll
    for (int j = 0; j < 4; j++)
        tile[y + j * 8][x] = W[(size_t)(k0 + y + j * 8) * N + n0 + x];
    __syncthreads();
#pragma unroll
    for (int j = 0; j < 4; j++)
        Wt[(size_t)(n0 + y + j * 8) * K + k0 + x] =
            __float2half_rn(tile[x][y + j * 8]);
}

// ---------------------------------------------------------------------------
// inv_freq table (fp64 exp once)
// ---------------------------------------------------------------------------
__global__ void init_invfreq()
{
    const int i = threadIdx.x;
    g_invfreq[i] = (float)exp(-((double)(2 * i) / 256.0) * log(10000.0));
}

// ---------------------------------------------------------------------------
// RoPE -> fp16 (scale folded)
// ---------------------------------------------------------------------------
__global__ void rope16(const float* __restrict__ in, __half* __restrict__ out,
                       const int* __restrict__ pos_ids, int n_heads, float scale)
{
    const int idx = blockIdx.x * blockDim.x + threadIdx.x;
    const int tot = ROWS * n_heads * 128;
    if (idx >= tot) return;

    const int i   = idx & 127;
    const int t2  = idx >> 7;
    const int h   = t2 % n_heads;
    const int row = t2 / n_heads;

    const float ang = (float)pos_ids[row] * g_invfreq[i];
    float s, c;
    sincosf(ang, &s, &c);

    const int stride = n_heads * HD;
    const size_t base = (size_t)row * stride + h * HD;
    const float x1 = in[base + i];
    const float x2 = in[base + i + 128];
    out[base + i]       = __float2half_rn((x1 * c - x2 * s) * scale);
    out[base + i + 128] = __float2half_rn((x2 * c + x1 * s) * scale);
}

// ---------------------------------------------------------------------------
// V: fp32 [b*S][kvh*256+d] -> fp16 transposed [b*kvh][dim][key]
// ---------------------------------------------------------------------------
__global__ void vtrans(const float* __restrict__ V, __half* __restrict__ Vt)
{
    const int idx = blockIdx.x * blockDim.x + threadIdx.x;
    if (idx >= 2 * NKV * HD * SQ) return;
    const int s   = idx & (SQ - 1);
    const int d   = (idx >> 11) & (HD - 1);
    const int bk  = idx >> 19;
    const int b   = bk >> 2, kvh = bk & 3;
    const float v = V[((size_t)(b * SQ + s)) * KCOLS + kvh * HD + d];
    Vt[((size_t)bk * HD + d) * SQ + s] = __float2half_rn(v);
}

// ---------------------------------------------------------------------------
// fp16 tensor-core causal flash attention (proven in R8). Output now fp16.
// Grid (32, NH, B), 128 threads = 4 warps. Br=64, Bc=64, D=256.
// ---------------------------------------------------------------------------
#define QK_LDH 264
#define VT_LDH 72
#define FL_SMEM_BYTES ((2 * 64 * QK_LDH + 256 * VT_LDH) * 2)

__global__ __launch_bounds__(128) void flash16(
    const __half* __restrict__ Q, const __half* __restrict__ K,
    const __half* __restrict__ Vt, __half* __restrict__ O)
{
    extern __shared__ __half sh[];
    __half* Qs = sh;
    __half* Ks = Qs + 64 * QK_LDH;
    __half* Vs = Ks + 64 * QK_LDH;

    const int tid  = threadIdx.x;
    const int lane = tid & 31;
    const int w    = tid >> 5;
    const int g    = lane >> 2;
    const int tg   = lane & 3;
    const int qt   = 31 - blockIdx.x;
    const int h    = blockIdx.y;
    const int b    = blockIdx.z;
    const int kvh  = h >> 2;
    const int qrow0 = qt * 64;
    const int wr   = w * 16;

    {
        const __half* Qg = Q + (size_t)(b * SQ + qrow0) * QCOLS + h * HD;
#pragma unroll
        for (int it = 0; it < 16; it++) {
            const int idx = tid + it * 128;
            const int r = idx >> 5, c8 = idx & 31;
            *(uint4*)&Qs[r * QK_LDH + c8 * 8] =
                *(const uint4*)&Qg[(size_t)r * QCOLS + c8 * 8];
        }
    }

    float o[32][4];
#pragma unroll
    for (int jd = 0; jd < 32; jd++)
#pragma unroll
        for (int e = 0; e < 4; e++) o[jd][e] = 0.f;
    float m0 = -1e30f, m1 = -1e30f, l0 = 0.f, l1 = 0.f;
    __syncthreads();

    for (int kt = 0; kt <= qt; kt++) {
        {
            const __half* Kg = K + (size_t)(b * SQ + kt * 64) * KCOLS + kvh * HD;
            const __half* Vg = Vt + ((size_t)(b * NKV + kvh) * HD) * SQ + kt * 64;
#pragma unroll
            for (int it = 0; it < 16; it++) {
                const int idx = tid + it * 128;
                const int r = idx >> 5, c8 = idx & 31;
                *(uint4*)&Ks[r * QK_LDH + c8 * 8] =
                    *(const uint4*)&Kg[(size_t)r * KCOLS + c8 * 8];
                const int d = idx >> 3, k8 = idx & 7;
                *(uint4*)&Vs[d * VT_LDH + k8 * 8] =
                    *(const uint4*)&Vg[(size_t)d * SQ + k8 * 8];
            }
        }
        __syncthreads();

        float s[8][4];
#pragma unroll
        for (int j = 0; j < 8; j++)
#pragma unroll
            for (int e = 0; e < 4; e++) s[j][e] = 0.f;

#pragma unroll
        for (int kc = 0; kc < 16; kc++) {
            uint32_t a[4];
            a[0] = *(const uint32_t*)&Qs[(wr + g)     * QK_LDH + kc * 16 + 2 * tg];
            a[1] = *(const uint32_t*)&Qs[(wr + g + 8) * QK_LDH + kc * 16 + 2 * tg];
            a[2] = *(const uint32_t*)&Qs[(wr + g)     * QK_LDH + kc * 16 + 2 * tg + 8];
            a[3] = *(const uint32_t*)&Qs[(wr + g + 8) * QK_LDH + kc * 16 + 2 * tg + 8];
#pragma unroll
            for (int j = 0; j < 8; j++) {
                uint32_t bf[2];
                bf[0] = *(const uint32_t*)&Ks[(j * 8 + g) * QK_LDH + kc * 16 + 2 * tg];
                bf[1] = *(const uint32_t*)&Ks[(j * 8 + g) * QK_LDH + kc * 16 + 2 * tg + 8];
                MMA_FP16(s[j], a, bf);
            }
        }

        if (kt == qt) {
            const int r0 = wr + g, r1 = wr + g + 8;
#pragma unroll
            for (int j = 0; j < 8; j++) {
                const int c0 = j * 8 + 2 * tg, c1 = c0 + 1;
                if (c0 > r0) s[j][0] = -1e30f;
                if (c1 > r0) s[j][1] = -1e30f;
                if (c0 > r1) s[j][2] = -1e30f;
                if (c1 > r1) s[j][3] = -1e30f;
            }
        }

        float tm0 = -1e30f, tm1 = -1e30f;
#pragma unroll
        for (int j = 0; j < 8; j++) {
            tm0 = fmaxf(tm0, fmaxf(s[j][0], s[j][1]));
            tm1 = fmaxf(tm1, fmaxf(s[j][2], s[j][3]));
        }
        tm0 = fmaxf(tm0, __shfl_xor_sync(0xffffffffu, tm0, 1));
        tm0 = fmaxf(tm0, __shfl_xor_sync(0xffffffffu, tm0, 2));
        tm1 = fmaxf(tm1, __shfl_xor_sync(0xffffffffu, tm1, 1));
        tm1 = fmaxf(tm1, __shfl_xor_sync(0xffffffffu, tm1, 2));

        const float mn0 = fmaxf(m0, tm0), mn1 = fmaxf(m1, tm1);
        const float cf0 = __expf(m0 - mn0), cf1 = __expf(m1 - mn1);
        m0 = mn0; m1 = mn1;

        uint32_t pf[8][2];
        float ls0 = 0.f, ls1 = 0.f;
#pragma unroll
        for (int j = 0; j < 8; j++) {
            const float p00 = __expf(s[j][0] - m0);
            const float p01 = __expf(s[j][1] - m0);
            const float p10 = __expf(s[j][2] - m1);
            const float p11 = __expf(s[j][3] - m1);
            ls0 += p00 + p01;
            ls1 += p10 + p11;
            pf[j][0] = pack_half2(p00, p01);
            pf[j][1] = pack_half2(p10, p11);
        }
        ls0 += __shfl_xor_sync(0xffffffffu, ls0, 1);
        ls0 += __shfl_xor_sync(0xffffffffu, ls0, 2);
        ls1 += __shfl_xor_sync(0xffffffffu, ls1, 1);
        ls1 += __shfl_xor_sync(0xffffffffu, ls1, 2);
        l0 = l0 * cf0 + ls0;
        l1 = l1 * cf1 + ls1;

#pragma unroll
        for (int jd = 0; jd < 32; jd++) {
            o[jd][0] *= cf0; o[jd][1] *= cf0;
            o[jd][2] *= cf1; o[jd][3] *= cf1;
        }
#pragma unroll
        for (int kc = 0; kc < 4; kc++) {
            uint32_t a[4] = { pf[2 * kc][0], pf[2 * kc][1],
                              pf[2 * kc + 1][0], pf[2 * kc + 1][1] };
#pragma unroll
            for (int jd = 0; jd < 32; jd++) {
                uint32_t bf[2];
                bf[0] = *(const uint32_t*)&Vs[(jd * 8 + g) * VT_LDH + kc * 16 + 2 * tg];
                bf[1] = *(const uint32_t*)&Vs[(jd * 8 + g) * VT_LDH + kc * 16 + 2 * tg + 8];
                MMA_FP16(o[jd], a, bf);
            }
        }
        __syncthreads();
    }

    // Normalize + store fp16 (feeds O-projection GEMM)
    const float inv0 = 1.0f / l0, inv1 = 1.0f / l1;
    const size_t r0 = (size_t)(b * SQ + qrow0 + wr + g) * QCOLS + h * HD;
    const size_t r1 = (size_t)(b * SQ + qrow0 + wr + g + 8) * QCOLS + h * HD;
#pragma unroll
    for (int jd = 0; jd < 32; jd++) {
        const int cc = jd * 8 + 2 * tg;
        *(uint32_t*)&O[r0 + cc] = pack_half2(o[jd][0] * inv0, o[jd][1] * inv0);
        *(uint32_t*)&O[r1 + cc] = pack_half2(o[jd][2] * inv1, o[jd][3] * inv1);
    }
}

// ---------------------------------------------------------------------------
// Launch. inputs: hidden_states, attention_mask, position_ids, Wq, Wk, Wv, Wo
// ---------------------------------------------------------------------------
extern "C" void kernel_launch(void* const* d_in, const int* in_sizes, int n_in,
                              void* d_out, int out_size)
{
    const float* X   = (const float*)d_in[0];
    const int*   pos = (const int*)d_in[2];
    const float* Wq  = (const float*)d_in[3];
    const float* Wk  = (const float*)d_in[4];
    const float* Wv  = (const float*)d_in[5];
    const float* Wo  = (const float*)d_in[6];
    float* out = (float*)d_out;

    float *Qb, *Kb, *Vb;
    __half *Qh, *Kh, *Vth, *Ah, *Xh, *WqT, *WkT, *WvT, *WoT;
    cudaGetSymbolAddress((void**)&Qb,  g_Q);
    cudaGetSymbolAddress((void**)&Kb,  g_K);
    cudaGetSymbolAddress((void**)&Vb,  g_V);
    cudaGetSymbolAddress((void**)&Qh,  g_Qh);
    cudaGetSymbolAddress((void**)&Kh,  g_Kh);
    cudaGetSymbolAddress((void**)&Vth, g_Vt);
    cudaGetSymbolAddress((void**)&Ah,  g_Ah);
    cudaGetSymbolAddress((void**)&Xh,  g_Xh);
    cudaGetSymbolAddress((void**)&WqT, g_WqT);
    cudaGetSymbolAddress((void**)&WkT, g_WkT);
    cudaGetSymbolAddress((void**)&WvT, g_WvT);
    cudaGetSymbolAddress((void**)&WoT, g_WoT);

    init_invfreq<<<1, 128>>>();

    // fp16 conversions: X and all weights (transposed to [N][K])
    f2h<<<(ROWS * HID / 4 + 255) / 256, 256>>>(X, Xh, ROWS * HID);
    wtrans<<<dim3(QCOLS / 32, HID / 32), dim3(32, 8)>>>(Wq, WqT, HID, QCOLS);
    wtrans<<<dim3(KCOLS / 32, HID / 32), dim3(32, 8)>>>(Wk, WkT, HID, KCOLS);
    wtrans<<<dim3(KCOLS / 32, HID / 32), dim3(32, 8)>>>(Wv, WvT, HID, KCOLS);
    wtrans<<<dim3(HID / 32, QCOLS / 32), dim3(32, 8)>>>(Wo, WoT, QCOLS, HID);

    // QKV projections (fp16 tensor cores, fp32 accumulate)
    cudaFuncSetAttribute(gemm_f16, cudaFuncAttributeMaxDynamicSharedMemorySize,
                         GEMM_SMEM_BYTES);
    gemm_f16<<<dim3(QCOLS / 128, ROWS / 128), 256, GEMM_SMEM_BYTES>>>(
        Xh, WqT, Qb, ROWS, QCOLS, HID);
    gemm_f16<<<dim3(KCOLS / 128, ROWS / 128), 256, GEMM_SMEM_BYTES>>>(
        Xh, WkT, Kb, ROWS, KCOLS, HID);
    gemm_f16<<<dim3(KCOLS / 128, ROWS / 128), 256, GEMM_SMEM_BYTES>>>(
        Xh, WvT, Vb, ROWS, KCOLS, HID);

    // RoPE -> fp16 (Q gets 1/sqrt(256) folded in); V -> fp16 transposed
    rope16<<<(ROWS * NH  * 128 + 255) / 256, 256>>>(Qb, Qh, pos, NH, 0.0625f);
    rope16<<<(ROWS * NKV * 128 + 255) / 256, 256>>>(Kb, Kh, pos, NKV, 1.0f);
    vtrans<<<(2 * NKV * HD * SQ + 255) / 256, 256>>>(Vb, Vth);

    // fp16 tensor-core causal flash attention -> fp16 output
    cudaFuncSetAttribute(flash16, cudaFuncAttributeMaxDynamicSharedMemorySize,
                         FL_SMEM_BYTES);
    flash16<<<dim3(SQ / 64, NH, 2), 128, FL_SMEM_BYTES>>>(Qh, Kh, Vth, Ah);

    // Output projection (fp16 tensor cores) -> fp32 final output
    gemm_f16<<<dim3(HID / 128, ROWS / 128), 256, GEMM_SMEM_BYTES>>>(
        Ah, WoT, out, ROWS, HID, QCOLS);
}

// round 11
// speedup vs baseline: 13.0658x; 1.0675x over previous
#include <cuda_runtime.h>
#include <cuda_fp16.h>
#include <math.h>
#include <stdint.h>

// ---------------------------------------------------------------------------
// Problem constants: B=2, S=2048, HID=2048, NH=16, NKV=4, HD=256
// ---------------------------------------------------------------------------
#define ROWS      4096
#define HID       2048
#define NH        16
#define NKV       4
#define HD        256
#define SQ        2048
#define QCOLS     (NH * HD)    // 4096
#define KCOLS     (NKV * HD)   // 1024

// Scratch (static device globals -- no allocation anywhere)
__device__ float  g_Q[(size_t)ROWS * QCOLS];
__device__ float  g_K[(size_t)ROWS * KCOLS];
__device__ float  g_V[(size_t)ROWS * KCOLS];
__device__ __half g_Qh[(size_t)ROWS * QCOLS];
__device__ __half g_Kh[(size_t)ROWS * KCOLS];
__device__ __half g_Vt[(size_t)(2 * NKV) * HD * SQ];
__device__ __half g_Ah[(size_t)ROWS * QCOLS];
__device__ __half g_Xh[(size_t)ROWS * HID];
__device__ __half g_WqT[(size_t)QCOLS * HID];
__device__ __half g_WkT[(size_t)KCOLS * HID];
__device__ __half g_WvT[(size_t)KCOLS * HID];
__device__ __half g_WoT[(size_t)HID * QCOLS];
__device__ float  g_invfreq[128];

// ---------------------------------------------------------------------------
// Helpers
// ---------------------------------------------------------------------------
__device__ __forceinline__ uint32_t pack_half2(float a, float b) {
    uint32_t r;
    asm("cvt.rn.f16x2.f32 %0, %2, %1;" : "=r"(r) : "f"(a), "f"(b));
    return r;
}

__device__ __forceinline__ void cpa16(uint32_t saddr, const void* gaddr) {
    asm volatile("cp.async.cg.shared.global [%0], [%1], 16;"
                 :: "r"(saddr), "l"(gaddr));
}
#define CP_COMMIT() asm volatile("cp.async.commit_group;")
#define CP_WAIT1()  asm volatile("cp.async.wait_group 1;")

__device__ __forceinline__ void ldsm_x4(uint32_t* r, uint32_t saddr) {
    asm volatile("ldmatrix.sync.aligned.m8n8.x4.shared.b16 {%0,%1,%2,%3}, [%4];"
                 : "=r"(r[0]), "=r"(r[1]), "=r"(r[2]), "=r"(r[3])
                 : "r"(saddr));
}

#define MMA_FP16(d, a, b)                                                      \
    asm volatile(                                                              \
        "mma.sync.aligned.m16n8k16.row.col.f32.f16.f16.f32 "                   \
        "{%0,%1,%2,%3},{%4,%5,%6,%7},{%8,%9},{%0,%1,%2,%3};"                   \
        : "+f"((d)[0]), "+f"((d)[1]), "+f"((d)[2]), "+f"((d)[3])               \
        : "r"((a)[0]), "r"((a)[1]), "r"((a)[2]), "r"((a)[3]),                  \
          "r"((b)[0]), "r"((b)[1]))

// ---------------------------------------------------------------------------
// fp16 tensor-core GEMM: C[M,N] = A[M,K] @ Bt[N,K]^T  (both row-major in K).
// 128x128 block tile, BK=32, 256 threads = 8 warps (2x4), warp tile 64x32.
// 3-stage cp.async pipeline; ldmatrix fragment loads (stride 40 halves =
// conflict-free: row addresses 5*16B apart cover all 8 16B banks).
// ---------------------------------------------------------------------------
#define GLDK   40
#define GSTG   (128 * GLDK)            // halves per matrix per stage (5120)
#define GBOFF  (3 * GSTG)              // Bs base (halves)
#define GEMM_SMEM_BYTES (6 * GSTG * 2) // 61440

__global__ __launch_bounds__(256) void gemm_f16(
    const __half* __restrict__ A, const __half* __restrict__ Bt,
    float* __restrict__ C, int M, int N, int K)
{
    extern __shared__ __half sh[];

    const int tid  = threadIdx.x;
    const int wid  = tid >> 5;
    const int lane = tid & 31;
    const int g    = lane >> 2;
    const int tg   = lane & 3;
    const int wm   = (wid & 1) * 64;
    const int wn   = (wid >> 1) * 32;
    const int row0 = blockIdx.y * 128;
    const int col0 = blockIdx.x * 128;

    const int r0  = tid >> 2;
    const int kc0 = (tid & 3) * 8;

    const __half* Ag0 = A  + (size_t)(row0 + r0)      * K + kc0;
    const __half* Ag1 = A  + (size_t)(row0 + r0 + 64) * K + kc0;
    const __half* Bg0 = Bt + (size_t)(col0 + r0)      * K + kc0;
    const __half* Bg1 = Bt + (size_t)(col0 + r0 + 64) * K + kc0;

    const uint32_t sbase = (uint32_t)__cvta_generic_to_shared(sh);
    const uint32_t aoff  = (uint32_t)(r0 * GLDK + kc0) * 2;
    const uint32_t rstep = 64 * GLDK * 2;

    // ldmatrix per-lane offsets (bytes within a stage slice)
    const uint32_t a_lm = (uint32_t)((wm + (lane & 15)) * GLDK +
                                     (lane >> 4) * 8) * 2;
    const uint32_t b_lm = (uint32_t)((wn + (lane >> 4) * 8 + (lane & 7)) * GLDK +
                                     ((lane >> 3) & 1) * 8) * 2;

    float acc[4][4][4];
#pragma unroll
    for (int mi = 0; mi < 4; mi++)
#pragma unroll
        for (int ni = 0; ni < 4; ni++)
#pragma unroll
            for (int e = 0; e < 4; e++) acc[mi][ni][e] = 0.f;

    const int nk = K >> 5;             // BK = 32

#pragma unroll
    for (int p = 0; p < 2; p++) {
        const uint32_t sa = sbase + (uint32_t)(p * GSTG) * 2 + aoff;
        const uint32_t sb = sbase + (uint32_t)((GBOFF + p * GSTG)) * 2 + aoff;
        const size_t ko = (size_t)p * 32;
        cpa16(sa,         Ag0 + ko);
        cpa16(sa + rstep, Ag1 + ko);
        cpa16(sb,         Bg0 + ko);
        cpa16(sb + rstep, Bg1 + ko);
        CP_COMMIT();
    }

    for (int kt = 0; kt < nk; kt++) {
        CP_WAIT1();
        __syncthreads();

        if (kt + 2 < nk) {
            const int st2 = (kt + 2) % 3;
            const uint32_t sa = sbase + (uint32_t)(st2 * GSTG) * 2 + aoff;
            const uint32_t sb = sbase + (uint32_t)((GBOFF + st2 * GSTG)) * 2 + aoff;
            const size_t ko = (size_t)(kt + 2) * 32;
            cpa16(sa,         Ag0 + ko);
            cpa16(sa + rstep, Ag1 + ko);
            cpa16(sb,         Bg0 + ko);
            cpa16(sb + rstep, Bg1 + ko);
        }
        CP_COMMIT();

        const uint32_t sAl = sbase + (uint32_t)((kt % 3) * GSTG) * 2;
        const uint32_t sBl = sbase + (uint32_t)((GBOFF + (kt % 3) * GSTG)) * 2;
#pragma unroll
        for (int kc = 0; kc < 2; kc++) {
            uint32_t af[4][4], bf[4][2];
#pragma unroll
            for (int mi = 0; mi < 4; mi++)
                ldsm_x4(af[mi], sAl + a_lm + (uint32_t)(mi * 16 * GLDK + kc * 16) * 2);
#pragma unroll
            for (int p = 0; p < 2; p++) {
                uint32_t bq[4];
                ldsm_x4(bq, sBl + b_lm + (uint32_t)(p * 16 * GLDK + kc * 16) * 2);
                bf[2 * p][0]     = bq[0];
                bf[2 * p][1]     = bq[1];
                bf[2 * p + 1][0] = bq[2];
                bf[2 * p + 1][1] = bq[3];
            }
#pragma unroll
            for (int mi = 0; mi < 4; mi++)
#pragma unroll
                for (int ni = 0; ni < 4; ni++)
                    MMA_FP16(acc[mi][ni], af[mi], bf[ni]);
        }
        __syncthreads();
    }

#pragma unroll
    for (int mi = 0; mi < 4; mi++) {
#pragma unroll
        for (int ni = 0; ni < 4; ni++) {
            const int r  = row0 + wm + mi * 16 + g;
            const int cc = col0 + wn + ni * 8 + tg * 2;
            *(float2*)&C[(size_t)r * N + cc] =
                make_float2(acc[mi][ni][0], acc[mi][ni][1]);
            *(float2*)&C[(size_t)(r + 8) * N + cc] =
                make_float2(acc[mi][ni][2], acc[mi][ni][3]);
        }
    }
}

// ---------------------------------------------------------------------------
// fp32 -> fp16 (vectorized)
// ---------------------------------------------------------------------------
__global__ void f2h(const float* __restrict__ in, __half* __restrict__ out, int n)
{
    const int i = blockIdx.x * blockDim.x + threadIdx.x;
    if (i * 4 >= n) return;
    const float4 v = ((const float4*)in)[i];
    uint2 h;
    h.x = pack_half2(v.x, v.y);
    h.y = pack_half2(v.z, v.w);
    ((uint2*)out)[i] = h;
}

// ---------------------------------------------------------------------------
// Weight transpose+convert: W[K][N] fp32 -> Wt[N][K] fp16
// ---------------------------------------------------------------------------
__global__ void wtrans(const float* __restrict__ W, __half* __restrict__ Wt,
                       int K, int N)
{
    __shared__ float tile[32][33];
    const int x = threadIdx.x, y = threadIdx.y;
    const int n0 = blockIdx.x * 32, k0 = blockIdx.y * 32;
#pragma unroll
    for (int j = 0; j < 4; j++)
        tile[y + j * 8][x] = W[(size_t)(k0 + y + j * 8) * N + n0 + x];
    __syncthreads();
#pragma unroll
    for (int j = 0; j < 4; j++)
        Wt[(size_t)(n0 + y + j * 8) * K + k0 + x] =
            __float2half_rn(tile[x][y + j * 8]);
}

// ---------------------------------------------------------------------------
// inv_freq table (fp64 exp once)
// ---------------------------------------------------------------------------
__global__ void init_invfreq()
{
    const int i = threadIdx.x;
    g_invfreq[i] = (float)exp(-((double)(2 * i) / 256.0) * log(10000.0));
}

// ---------------------------------------------------------------------------
// RoPE -> fp16 (scale folded)
// ---------------------------------------------------------------------------
__global__ void rope16(const float* __restrict__ in, __half* __restrict__ out,
                       const int* __restrict__ pos_ids, int n_heads, float scale)
{
    const int idx = blockIdx.x * blockDim.x + threadIdx.x;
    const int tot = ROWS * n_heads * 128;
    if (idx >= tot) return;

    const int i   = idx & 127;
    const int t2  = idx >> 7;
    const int h   = t2 % n_heads;
    const int row = t2 / n_heads;

    const float ang = (float)pos_ids[row] * g_invfreq[i];
    float s, c;
    sincosf(ang, &s, &c);

    const int stride = n_heads * HD;
    const size_t base = (size_t)row * stride + h * HD;
    const float x1 = in[base + i];
    const float x2 = in[base + i + 128];
    out[base + i]       = __float2half_rn((x1 * c - x2 * s) * scale);
    out[base + i + 128] = __float2half_rn((x2 * c + x1 * s) * scale);
}

// ---------------------------------------------------------------------------
// V transpose (coalesced): fp32 [b*S][kvh*256+d] -> fp16 [b*kvh][d][s]
// ---------------------------------------------------------------------------
__global__ void vtrans(const float* __restrict__ V, __half* __restrict__ Vt)
{
    __shared__ float tile[32][33];
    const int s0 = blockIdx.x * 32, d0 = blockIdx.y * 32, bk = blockIdx.z;
    const int b = bk >> 2, kvh = bk & 3;
    const int x = threadIdx.x, y = threadIdx.y;
#pragma unroll
    for (int j = 0; j < 4; j++)
        tile[y + j * 8][x] =
            V[(size_t)(b * SQ + s0 + y + j * 8) * KCOLS + kvh * HD + d0 + x];
    __syncthreads();
#pragma unroll
    for (int j = 0; j < 4; j++)
        Vt[((size_t)bk * HD + d0 + y + j * 8) * SQ + s0 + x] =
            __float2half_rn(tile[x][y + j * 8]);
}

// ---------------------------------------------------------------------------
// fp16 tensor-core causal flash attention, ldmatrix fragment loads.
// Grid (32, NH, B), 128 threads = 4 warps. Br=64, Bc=64, D=256. fp16 out.
// ---------------------------------------------------------------------------
#define QK_LDH 264   // 33 x 16B rows -> conflict-free ldmatrix
#define VT_LDH 72    // 9 x 16B rows  -> conflict-free ldmatrix
#define FL_SMEM_BYTES ((2 * 64 * QK_LDH + 256 * VT_LDH) * 2)

__global__ __launch_bounds__(128) void flash16(
    const __half* __restrict__ Q, const __half* __restrict__ K,
    const __half* __restrict__ Vt, __half* __restrict__ O)
{
    extern __shared__ __half sh[];
    __half* Qs = sh;
    __half* Ks = Qs + 64 * QK_LDH;
    __half* Vs = Ks + 64 * QK_LDH;

    const int tid  = threadIdx.x;
    const int lane = tid & 31;
    const int w    = tid >> 5;
    const int g    = lane >> 2;
    const int tg   = lane & 3;
    const int qt   = 31 - blockIdx.x;
    const int h    = blockIdx.y;
    const int b    = blockIdx.z;
    const int kvh  = h >> 2;
    const int qrow0 = qt * 64;
    const int wr   = w * 16;

    // ldmatrix per-lane base offsets (bytes)
    const uint32_t q_lm = (uint32_t)((wr + (lane & 15)) * QK_LDH +
                                     (lane >> 4) * 8) * 2;
    const uint32_t k_lm = (uint32_t)(((lane >> 4) * 8 + (lane & 7)) * QK_LDH +
                                     ((lane >> 3) & 1) * 8) * 2;
    const uint32_t v_lm = (uint32_t)(((lane >> 4) * 8 + (lane & 7)) * VT_LDH +
                                     ((lane >> 3) & 1) * 8) * 2;
    const uint32_t sQ = (uint32_t)__cvta_generic_to_shared(Qs) + q_lm;
    const uint32_t sK = (uint32_t)__cvta_generic_to_shared(Ks) + k_lm;
    const uint32_t sV = (uint32_t)__cvta_generic_to_shared(Vs) + v_lm;

    {
        const __half* Qg = Q + (size_t)(b * SQ + qrow0) * QCOLS + h * HD;
#pragma unroll
        for (int it = 0; it < 16; it++) {
            const int idx = tid + it * 128;
            const int r = idx >> 5, c8 = idx & 31;
            *(uint4*)&Qs[r * QK_LDH + c8 * 8] =
                *(const uint4*)&Qg[(size_t)r * QCOLS + c8 * 8];
        }
    }

    float o[32][4];
#pragma unroll
    for (int jd = 0; jd < 32; jd++)
#pragma unroll
        for (int e = 0; e < 4; e++) o[jd][e] = 0.f;
    float m0 = -1e30f, m1 = -1e30f, l0 = 0.f, l1 = 0.f;
    __syncthreads();

    for (int kt = 0; kt <= qt; kt++) {
        {
            const __half* Kg = K + (size_t)(b * SQ + kt * 64) * KCOLS + kvh * HD;
            const __half* Vg = Vt + ((size_t)(b * NKV + kvh) * HD) * SQ + kt * 64;
#pragma unroll
            for (int it = 0; it < 16; it++) {
                const int idx = tid + it * 128;
                const int r = idx >> 5, c8 = idx & 31;
                *(uint4*)&Ks[r * QK_LDH + c8 * 8] =
                    *(const uint4*)&Kg[(size_t)r * KCOLS + c8 * 8];
                const int d = idx >> 3, k8 = idx & 7;
                *(uint4*)&Vs[d * VT_LDH + k8 * 8] =
                    *(const uint4*)&Vg[(size_t)d * SQ + k8 * 8];
            }
        }
        __syncthreads();

        // S = Q K^T
        float s[8][4];
#pragma unroll
        for (int j = 0; j < 8; j++)
#pragma unroll
            for (int e = 0; e < 4; e++) s[j][e] = 0.f;

#pragma unroll
        for (int kc = 0; kc < 16; kc++) {
            uint32_t a[4];
            ldsm_x4(a, sQ + (uint32_t)(kc * 16) * 2);
#pragma unroll
            for (int p = 0; p < 4; p++) {
                uint32_t kq[4];
                ldsm_x4(kq, sK + (uint32_t)(p * 16 * QK_LDH + kc * 16) * 2);
                MMA_FP16(s[2 * p],     a, (kq + 0));
                MMA_FP16(s[2 * p + 1], a, (kq + 2));
            }
        }

        if (kt == qt) {
            const int r0 = wr + g, r1 = wr + g + 8;
#pragma unroll
            for (int j = 0; j < 8; j++) {
                const int c0 = j * 8 + 2 * tg, c1 = c0 + 1;
                if (c0 > r0) s[j][0] = -1e30f;
                if (c1 > r0) s[j][1] = -1e30f;
                if (c0 > r1) s[j][2] = -1e30f;
                if (c1 > r1) s[j][3] = -1e30f;
            }
        }

        float tm0 = -1e30f, tm1 = -1e30f;
#pragma unroll
        for (int j = 0; j < 8; j++) {
            tm0 = fmaxf(tm0, fmaxf(s[j][0], s[j][1]));
            tm1 = fmaxf(tm1, fmaxf(s[j][2], s[j][3]));
        }
        tm0 = fmaxf(tm0, __shfl_xor_sync(0xffffffffu, tm0, 1));
        tm0 = fmaxf(tm0, __shfl_xor_sync(0xffffffffu, tm0, 2));
        tm1 = fmaxf(tm1, __shfl_xor_sync(0xffffffffu, tm1, 1));
        tm1 = fmaxf(tm1, __shfl_xor_sync(0xffffffffu, tm1, 2));

        const float mn0 = fmaxf(m0, tm0), mn1 = fmaxf(m1, tm1);
        const float cf0 = __expf(m0 - mn0), cf1 = __expf(m1 - mn1);
        m0 = mn0; m1 = mn1;

        uint32_t pf[8][2];
        float ls0 = 0.f, ls1 = 0.f;
#pragma unroll
        for (int j = 0; j < 8; j++) {
            const float p00 = __expf(s[j][0] - m0);
            const float p01 = __expf(s[j][1] - m0);
            const float p10 = __expf(s[j][2] - m1);
            const float p11 = __expf(s[j][3] - m1);
            ls0 += p00 + p01;
            ls1 += p10 + p11;
            pf[j][0] = pack_half2(p00, p01);
            pf[j][1] = pack_half2(p10, p11);
        }
        ls0 += __shfl_xor_sync(0xffffffffu, ls0, 1);
        ls0 += __shfl_xor_sync(0xffffffffu, ls0, 2);
        ls1 += __shfl_xor_sync(0xffffffffu, ls1, 1);
        ls1 += __shfl_xor_sync(0xffffffffu, ls1, 2);
        l0 = l0 * cf0 + ls0;
        l1 = l1 * cf1 + ls1;

#pragma unroll
        for (int jd = 0; jd < 32; jd++) {
            o[jd][0] *= cf0; o[jd][1] *= cf0;
            o[jd][2] *= cf1; o[jd][3] *= cf1;
        }
        // O += P V  (V fragments via ldmatrix, 2 MMAs per x4)
#pragma unroll
        for (int kc = 0; kc < 4; kc++) {
            uint32_t a[4] = { pf[2 * kc][0], pf[2 * kc][1],
                              pf[2 * kc + 1][0], pf[2 * kc + 1][1] };
#pragma unroll
            for (int p = 0; p < 16; p++) {
                uint32_t vq[4];
                ldsm_x4(vq, sV + (uint32_t)(p * 16 * VT_LDH + kc * 16) * 2);
                MMA_FP16(o[2 * p],     a, (vq + 0));
                MMA_FP16(o[2 * p + 1], a, (vq + 2));
            }
        }
        __syncthreads();
    }

    const float inv0 = 1.0f / l0, inv1 = 1.0f / l1;
    const size_t r0 = (size_t)(b * SQ + qrow0 + wr + g) * QCOLS + h * HD;
    const size_t r1 = (size_t)(b * SQ + qrow0 + wr + g + 8) * QCOLS + h * HD;
#pragma unroll
    for (int jd = 0; jd < 32; jd++) {
        const int cc = jd * 8 + 2 * tg;
        *(uint32_t*)&O[r0 + cc] = pack_half2(o[jd][0] * inv0, o[jd][1] * inv0);
        *(uint32_t*)&O[r1 + cc] = pack_half2(o[jd][2] * inv1, o[jd][3] * inv1);
    }
}

// ---------------------------------------------------------------------------
// Launch. inputs: hidden_states, attention_mask, position_ids, Wq, Wk, Wv, Wo
// ---------------------------------------------------------------------------
extern "C" void kernel_launch(void* const* d_in, const int* in_sizes, int n_in,
                              void* d_out, int out_size)
{
    const float* X   = (const float*)d_in[0];
    const int*   pos = (const int*)d_in[2];
    const float* Wq  = (const float*)d_in[3];
    const float* Wk  = (const float*)d_in[4];
    const float* Wv  = (const float*)d_in[5];
    const float* Wo  = (const float*)d_in[6];
    float* out = (float*)d_out;

    float *Qb, *Kb, *Vb;
    __half *Qh, *Kh, *Vth, *Ah, *Xh, *WqT, *WkT, *WvT, *WoT;
    cudaGetSymbolAddress((void**)&Qb,  g_Q);
    cudaGetSymbolAddress((void**)&Kb,  g_K);
    cudaGetSymbolAddress((void**)&Vb,  g_V);
    cudaGetSymbolAddress((void**)&Qh,  g_Qh);
    cudaGetSymbolAddress((void**)&Kh,  g_Kh);
    cudaGetSymbolAddress((void**)&Vth, g_Vt);
    cudaGetSymbolAddress((void**)&Ah,  g_Ah);
    cudaGetSymbolAddress((void**)&Xh,  g_Xh);
    cudaGetSymbolAddress((void**)&WqT, g_WqT);
    cudaGetSymbolAddress((void**)&WkT, g_WkT);
    cudaGetSymbolAddress((void**)&WvT, g_WvT);
    cudaGetSymbolAddress((void**)&WoT, g_WoT);

    init_invfreq<<<1, 128>>>();

    // fp16 conversions: X and all weights (transposed to [N][K])
    f2h<<<(ROWS * HID / 4 + 255) / 256, 256>>>(X, Xh, ROWS * HID);
    wtrans<<<dim3(QCOLS / 32, HID / 32), dim3(32, 8)>>>(Wq, WqT, HID, QCOLS);
    wtrans<<<dim3(KCOLS / 32, HID / 32), dim3(32, 8)>>>(Wk, WkT, HID, KCOLS);
    wtrans<<<dim3(KCOLS / 32, HID / 32), dim3(32, 8)>>>(Wv, WvT, HID, KCOLS);
    wtrans<<<dim3(HID / 32, QCOLS / 32), dim3(32, 8)>>>(Wo, WoT, QCOLS, HID);

    // QKV projections (fp16 tensor cores, fp32 accumulate)
    cudaFuncSetAttribute(gemm_f16, cudaFuncAttributeMaxDynamicSharedMemorySize,
                         GEMM_SMEM_BYTES);
    gemm_f16<<<dim3(QCOLS / 128, ROWS / 128), 256, GEMM_SMEM_BYTES>>>(
        Xh, WqT, Qb, ROWS, QCOLS, HID);
    gemm_f16<<<dim3(KCOLS / 128, ROWS / 128), 256, GEMM_SMEM_BYTES>>>(
        Xh, WkT, Kb, ROWS, KCOLS, HID);
    gemm_f16<<<dim3(KCOLS / 128, ROWS / 128), 256, GEMM_SMEM_BYTES>>>(
        Xh, WvT, Vb, ROWS, KCOLS, HID);

    // RoPE -> fp16 (Q gets 1/sqrt(256) folded in); V -> fp16 transposed
    rope16<<<(ROWS * NH  * 128 + 255) / 256, 256>>>(Qb, Qh, pos, NH, 0.0625f);
    rope16<<<(ROWS * NKV * 128 + 255) / 256, 256>>>(Kb, Kh, pos, NKV, 1.0f);
    vtrans<<<dim3(SQ / 32, HD / 32, 2 * NKV), dim3(32, 8)>>>(Vb, Vth);

    // fp16 tensor-core causal flash attention -> fp16 output
    cudaFuncSetAttribute(flash16, cudaFuncAttributeMaxDynamicSharedMemorySize,
                         FL_SMEM_BYTES);
    flash16<<<dim3(SQ / 64, NH, 2), 128, FL_SMEM_BYTES>>>(Qh, Kh, Vth, Ah);

    // Output projection (fp16 tensor cores) -> fp32 final output
    gemm_f16<<<dim3(HID / 128, ROWS / 128), 256, GEMM_SMEM_BYTES>>>(
        Ah, WoT, out, ROWS, HID, QCOLS);
}

// round 12
// speedup vs baseline: 14.3217x; 1.0961x over previous
#include <cuda_runtime.h>
#include <cuda_fp16.h>
#include <math.h>
#include <stdint.h>

// ---------------------------------------------------------------------------
// Problem constants: B=2, S=2048, HID=2048, NH=16, NKV=4, HD=256
// ---------------------------------------------------------------------------
#define ROWS      4096
#define HID       2048
#define NH        16
#define NKV       4
#define HD        256
#define SQ        2048
#define QCOLS     (NH * HD)    // 4096
#define KCOLS     (NKV * HD)   // 1024

// Scratch (static device globals -- no allocation anywhere)
__device__ float  g_Q[(size_t)ROWS * QCOLS];
__device__ float  g_K[(size_t)ROWS * KCOLS];
__device__ float  g_V[(size_t)ROWS * KCOLS];
__device__ __half g_Qh[(size_t)ROWS * QCOLS];
__device__ __half g_Kh[(size_t)ROWS * KCOLS];
__device__ __half g_Vt[(size_t)(2 * NKV) * HD * SQ];
__device__ __half g_Ah[(size_t)ROWS * QCOLS];
__device__ __half g_Xh[(size_t)ROWS * HID];
__device__ __half g_WqT[(size_t)QCOLS * HID];
__device__ __half g_WkT[(size_t)KCOLS * HID];
__device__ __half g_WvT[(size_t)KCOLS * HID];
__device__ __half g_WoT[(size_t)HID * QCOLS];
__device__ float  g_invfreq[128];

// ---------------------------------------------------------------------------
// Helpers
// ---------------------------------------------------------------------------
__device__ __forceinline__ uint32_t pack_half2(float a, float b) {
    uint32_t r;
    asm("cvt.rn.f16x2.f32 %0, %2, %1;" : "=r"(r) : "f"(a), "f"(b));
    return r;
}

__device__ __forceinline__ void cpa16(uint32_t saddr, const void* gaddr) {
    asm volatile("cp.async.cg.shared.global [%0], [%1], 16;"
                 :: "r"(saddr), "l"(gaddr));
}
#define CP_COMMIT() asm volatile("cp.async.commit_group;")
#define CP_WAIT1()  asm volatile("cp.async.wait_group 1;")

__device__ __forceinline__ void ldsm_x4(uint32_t* r, uint32_t saddr) {
    asm volatile("ldmatrix.sync.aligned.m8n8.x4.shared.b16 {%0,%1,%2,%3}, [%4];"
                 : "=r"(r[0]), "=r"(r[1]), "=r"(r[2]), "=r"(r[3])
                 : "r"(saddr));
}

#define MMA_FP16(d, a, b)                                                      \
    asm volatile(                                                              \
        "mma.sync.aligned.m16n8k16.row.col.f32.f16.f16.f32 "                   \
        "{%0,%1,%2,%3},{%4,%5,%6,%7},{%8,%9},{%0,%1,%2,%3};"                   \
        : "+f"((d)[0]), "+f"((d)[1]), "+f"((d)[2]), "+f"((d)[3])               \
        : "r"((a)[0]), "r"((a)[1]), "r"((a)[2]), "r"((a)[3]),                  \
          "r"((b)[0]), "r"((b)[1]))

// ---------------------------------------------------------------------------
// fp16 tensor-core GEMM: C[M,N] = A[M,K] @ Bt[N,K]^T  (both row-major in K).
// 128x128 block tile, BK=64, 256 threads = 8 warps (2x4), warp tile 64x32.
// 3-slot cp.async ring (prefetch distance 2), ONE __syncthreads per iter.
// smem row stride 72 halves = 9 x 16B -> conflict-free ldmatrix.
// ---------------------------------------------------------------------------
#define GLDK   72
#define GSTG   (128 * GLDK)            // halves per matrix per stage (9216)
#define GBOFF  (3 * GSTG)              // Bs base (halves)
#define GEMM_SMEM_BYTES (6 * GSTG * 2) // 110592

__device__ __forceinline__ void g_load_stage(
    uint32_t sbase, int slot, const __half* Ab, const __half* Bb,
    int K, int tid, int ko)
{
    const uint32_t ab = sbase + (uint32_t)(slot * GSTG) * 2;
    const uint32_t bb = sbase + (uint32_t)((GBOFF + slot * GSTG)) * 2;
#pragma unroll
    for (int i = 0; i < 4; i++) {
        const int c = tid + i * 256;          // 0..1023 chunk id
        const int row = c >> 3, col8 = c & 7; // 128 rows x 8 chunks
        const uint32_t so = (uint32_t)(row * GLDK + col8 * 8) * 2;
        cpa16(ab + so, Ab + (size_t)row * K + ko + col8 * 8);
        cpa16(bb + so, Bb + (size_t)row * K + ko + col8 * 8);
    }
}

__global__ __launch_bounds__(256) void gemm_f16(
    const __half* __restrict__ A, const __half* __restrict__ Bt,
    float* __restrict__ C, int M, int N, int K)
{
    extern __shared__ __half sh[];

    const int tid  = threadIdx.x;
    const int wid  = tid >> 5;
    const int lane = tid & 31;
    const int g    = lane >> 2;
    const int tg   = lane & 3;
    const int wm   = (wid & 1) * 64;
    const int wn   = (wid >> 1) * 32;
    const int row0 = blockIdx.y * 128;
    const int col0 = blockIdx.x * 128;

    const uint32_t sbase = (uint32_t)__cvta_generic_to_shared(sh);

    // ldmatrix per-lane offsets (bytes within a stage slice)
    const uint32_t a_lm = (uint32_t)((wm + (lane & 15)) * GLDK +
                                     (lane >> 4) * 8) * 2;
    const uint32_t b_lm = (uint32_t)((wn + (lane >> 4) * 8 + (lane & 7)) * GLDK +
                                     ((lane >> 3) & 1) * 8) * 2;

    float acc[4][4][4];
#pragma unroll
    for (int mi = 0; mi < 4; mi++)
#pragma unroll
        for (int ni = 0; ni < 4; ni++)
#pragma unroll
            for (int e = 0; e < 4; e++) acc[mi][ni][e] = 0.f;

    const __half* Abase = A  + (size_t)row0 * K;
    const __half* Bbase = Bt + (size_t)col0 * K;
    const int nk = K >> 6;             // BK = 64

    // prologue: stages 0, 1
    g_load_stage(sbase, 0, Abase, Bbase, K, tid, 0);
    CP_COMMIT();
    g_load_stage(sbase, 1, Abase, Bbase, K, tid, 64);
    CP_COMMIT();

    for (int kt = 0; kt < nk; kt++) {
        CP_WAIT1();
        __syncthreads();   // data of stage kt ready for ALL warps; also orders
                           // prior iter's reads before this iter's prefetch

        if (kt + 2 < nk)
            g_load_stage(sbase, (kt + 2) % 3, Abase, Bbase, K, tid,
                         (kt + 2) * 64);
        CP_COMMIT();

        const uint32_t sAl = sbase + (uint32_t)((kt % 3) * GSTG) * 2;
        const uint32_t sBl = sbase + (uint32_t)((GBOFF + (kt % 3) * GSTG)) * 2;
#pragma unroll
        for (int kc = 0; kc < 4; kc++) {
            uint32_t af[4][4], bf[4][2];
#pragma unroll
            for (int mi = 0; mi < 4; mi++)
                ldsm_x4(af[mi], sAl + a_lm + (uint32_t)(mi * 16 * GLDK + kc * 16) * 2);
#pragma unroll
            for (int p = 0; p < 2; p++) {
                uint32_t bq[4];
                ldsm_x4(bq, sBl + b_lm + (uint32_t)(p * 16 * GLDK + kc * 16) * 2);
                bf[2 * p][0]     = bq[0];
                bf[2 * p][1]     = bq[1];
                bf[2 * p + 1][0] = bq[2];
                bf[2 * p + 1][1] = bq[3];
            }
#pragma unroll
            for (int mi = 0; mi < 4; mi++)
#pragma unroll
                for (int ni = 0; ni < 4; ni++)
                    MMA_FP16(acc[mi][ni], af[mi], bf[ni]);
        }
        // NOTE: no end-of-loop __syncthreads -- top sync of next iter covers
        // the slot-reuse hazard (prefetch target == slot read last iter).
    }

#pragma unroll
    for (int mi = 0; mi < 4; mi++) {
#pragma unroll
        for (int ni = 0; ni < 4; ni++) {
            const int r  = row0 + wm + mi * 16 + g;
            const int cc = col0 + wn + ni * 8 + tg * 2;
            *(float2*)&C[(size_t)r * N + cc] =
                make_float2(acc[mi][ni][0], acc[mi][ni][1]);
            *(float2*)&C[(size_t)(r + 8) * N + cc] =
                make_float2(acc[mi][ni][2], acc[mi][ni][3]);
        }
    }
}

// ---------------------------------------------------------------------------
// fp32 -> fp16 (vectorized)
// ---------------------------------------------------------------------------
__global__ void f2h(const float* __restrict__ in, __half* __restrict__ out, int n)
{
    const int i = blockIdx.x * blockDim.x + threadIdx.x;
    if (i * 4 >= n) return;
    const float4 v = ((const float4*)in)[i];
    uint2 h;
    h.x = pack_half2(v.x, v.y);
    h.y = pack_half2(v.z, v.w);
    ((uint2*)out)[i] = h;
}

// ---------------------------------------------------------------------------
// Weight transpose+convert: W[K][N] fp32 -> Wt[N][K] fp16
// ---------------------------------------------------------------------------
__global__ void wtrans(const float* __restrict__ W, __half* __restrict__ Wt,
                       int K, int N)
{
    __shared__ float tile[32][33];
    const int x = threadIdx.x, y = threadIdx.y;
    const int n0 = blockIdx.x * 32, k0 = blockIdx.y * 32;
#pragma unroll
    for (int j = 0; j < 4; j++)
        tile[y + j * 8][x] = W[(size_t)(k0 + y + j * 8) * N + n0 + x];
    __syncthreads();
#pragma unroll
    for (int j = 0; j < 4; j++)
        Wt[(size_t)(n0 + y + j * 8) * K + k0 + x] =
            __float2half_rn(tile[x][y + j * 8]);
}

// ---------------------------------------------------------------------------
// inv_freq table (fp64 exp once)
// ---------------------------------------------------------------------------
__global__ void init_invfreq()
{
    const int i = threadIdx.x;
    g_invfreq[i] = (float)exp(-((double)(2 * i) / 256.0) * log(10000.0));
}

// ---------------------------------------------------------------------------
// RoPE -> fp16 (scale folded)
// ---------------------------------------------------------------------------
__global__ void rope16(const float* __restrict__ in, __half* __restrict__ out,
                       const int* __restrict__ pos_ids, int n_heads, float scale)
{
    const int idx = blockIdx.x * blockDim.x + threadIdx.x;
    const int tot = ROWS * n_heads * 128;
    if (idx >= tot) return;

    const int i   = idx & 127;
    const int t2  = idx >> 7;
    const int h   = t2 % n_heads;
    const int row = t2 / n_heads;

    const float ang = (float)pos_ids[row] * g_invfreq[i];
    float s, c;
    sincosf(ang, &s, &c);

    const int stride = n_heads * HD;
    const size_t base = (size_t)row * stride + h * HD;
    const float x1 = in[base + i];
    const float x2 = in[base + i + 128];
    out[base + i]       = __float2half_rn((x1 * c - x2 * s) * scale);
    out[base + i + 128] = __float2half_rn((x2 * c + x1 * s) * scale);
}

// ---------------------------------------------------------------------------
// V transpose (coalesced): fp32 [b*S][kvh*256+d] -> fp16 [b*kvh][d][s]
// ---------------------------------------------------------------------------
__global__ void vtrans(const float* __restrict__ V, __half* __restrict__ Vt)
{
    __shared__ float tile[32][33];
    const int s0 = blockIdx.x * 32, d0 = blockIdx.y * 32, bk = blockIdx.z;
    const int b = bk >> 2, kvh = bk & 3;
    const int x = threadIdx.x, y = threadIdx.y;
#pragma unroll
    for (int j = 0; j < 4; j++)
        tile[y + j * 8][x] =
            V[(size_t)(b * SQ + s0 + y + j * 8) * KCOLS + kvh * HD + d0 + x];
    __syncthreads();
#pragma unroll
    for (int j = 0; j < 4; j++)
        Vt[((size_t)bk * HD + d0 + y + j * 8) * SQ + s0 + x] =
            __float2half_rn(tile[x][y + j * 8]);
}

// ---------------------------------------------------------------------------
// fp16 tensor-core causal flash attention, ldmatrix fragment loads.
// Grid (32, NH, B), 128 threads = 4 warps. Br=64, Bc=64, D=256. fp16 out.
// ---------------------------------------------------------------------------
#define QK_LDH 264   // 33 x 16B rows -> conflict-free ldmatrix
#define VT_LDH 72    // 9 x 16B rows  -> conflict-free ldmatrix
#define FL_SMEM_BYTES ((2 * 64 * QK_LDH + 256 * VT_LDH) * 2)

__global__ __launch_bounds__(128) void flash16(
    const __half* __restrict__ Q, const __half* __restrict__ K,
    const __half* __restrict__ Vt, __half* __restrict__ O)
{
    extern __shared__ __half sh[];
    __half* Qs = sh;
    __half* Ks = Qs + 64 * QK_LDH;
    __half* Vs = Ks + 64 * QK_LDH;

    const int tid  = threadIdx.x;
    const int lane = tid & 31;
    const int w    = tid >> 5;
    const int g    = lane >> 2;
    const int tg   = lane & 3;
    const int qt   = 31 - blockIdx.x;
    const int h    = blockIdx.y;
    const int b    = blockIdx.z;
    const int kvh  = h >> 2;
    const int qrow0 = qt * 64;
    const int wr   = w * 16;

    const uint32_t q_lm = (uint32_t)((wr + (lane & 15)) * QK_LDH +
                                     (lane >> 4) * 8) * 2;
    const uint32_t k_lm = (uint32_t)(((lane >> 4) * 8 + (lane & 7)) * QK_LDH +
                                     ((lane >> 3) & 1) * 8) * 2;
    const uint32_t v_lm = (uint32_t)(((lane >> 4) * 8 + (lane & 7)) * VT_LDH +
                                     ((lane >> 3) & 1) * 8) * 2;
    const uint32_t sQ = (uint32_t)__cvta_generic_to_shared(Qs) + q_lm;
    const uint32_t sK = (uint32_t)__cvta_generic_to_shared(Ks) + k_lm;
    const uint32_t sV = (uint32_t)__cvta_generic_to_shared(Vs) + v_lm;

    {
        const __half* Qg = Q + (size_t)(b * SQ + qrow0) * QCOLS + h * HD;
#pragma unroll
        for (int it = 0; it < 16; it++) {
            const int idx = tid + it * 128;
            const int r = idx >> 5, c8 = idx & 31;
            *(uint4*)&Qs[r * QK_LDH + c8 * 8] =
                *(const uint4*)&Qg[(size_t)r * QCOLS + c8 * 8];
        }
    }

    float o[32][4];
#pragma unroll
    for (int jd = 0; jd < 32; jd++)
#pragma unroll
        for (int e = 0; e < 4; e++) o[jd][e] = 0.f;
    float m0 = -1e30f, m1 = -1e30f, l0 = 0.f, l1 = 0.f;
    __syncthreads();

    for (int kt = 0; kt <= qt; kt++) {
        {
            const __half* Kg = K + (size_t)(b * SQ + kt * 64) * KCOLS + kvh * HD;
            const __half* Vg = Vt + ((size_t)(b * NKV + kvh) * HD) * SQ + kt * 64;
#pragma unroll
            for (int it = 0; it < 16; it++) {
                const int idx = tid + it * 128;
                const int r = idx >> 5, c8 = idx & 31;
                *(uint4*)&Ks[r * QK_LDH + c8 * 8] =
                    *(const uint4*)&Kg[(size_t)r * KCOLS + c8 * 8];
                const int d = idx >> 3, k8 = idx & 7;
                *(uint4*)&Vs[d * VT_LDH + k8 * 8] =
                    *(const uint4*)&Vg[(size_t)d * SQ + k8 * 8];
            }
        }
        __syncthreads();

        float s[8][4];
#pragma unroll
        for (int j = 0; j < 8; j++)
#pragma unroll
            for (int e = 0; e < 4; e++) s[j][e] = 0.f;

#pragma unroll
        for (int kc = 0; kc < 16; kc++) {
            uint32_t a[4];
            ldsm_x4(a, sQ + (uint32_t)(kc * 16) * 2);
#pragma unroll
            for (int p = 0; p < 4; p++) {
                uint32_t kq[4];
                ldsm_x4(kq, sK + (uint32_t)(p * 16 * QK_LDH + kc * 16) * 2);
                MMA_FP16(s[2 * p],     a, (kq + 0));
                MMA_FP16(s[2 * p + 1], a, (kq + 2));
            }
        }

        if (kt == qt) {
            const int r0 = wr + g, r1 = wr + g + 8;
#pragma unroll
            for (int j = 0; j < 8; j++) {
                const int c0 = j * 8 + 2 * tg, c1 = c0 + 1;
                if (c0 > r0) s[j][0] = -1e30f;
                if (c1 > r0) s[j][1] = -1e30f;
                if (c0 > r1) s[j][2] = -1e30f;
                if (c1 > r1) s[j][3] = -1e30f;
            }
        }

        float tm0 = -1e30f, tm1 = -1e30f;
#pragma unroll
        for (int j = 0; j < 8; j++) {
            tm0 = fmaxf(tm0, fmaxf(s[j][0], s[j][1]));
            tm1 = fmaxf(tm1, fmaxf(s[j][2], s[j][3]));
        }
        tm0 = fmaxf(tm0, __shfl_xor_sync(0xffffffffu, tm0, 1));
        tm0 = fmaxf(tm0, __shfl_xor_sync(0xffffffffu, tm0, 2));
        tm1 = fmaxf(tm1, __shfl_xor_sync(0xffffffffu, tm1, 1));
        tm1 = fmaxf(tm1, __shfl_xor_sync(0xffffffffu, tm1, 2));

        const float mn0 = fmaxf(m0, tm0), mn1 = fmaxf(m1, tm1);
        const float cf0 = __expf(m0 - mn0), cf1 = __expf(m1 - mn1);
        m0 = mn0; m1 = mn1;

        uint32_t pf[8][2];
        float ls0 = 0.f, ls1 = 0.f;
#pragma unroll
        for (int j = 0; j < 8; j++) {
            const float p00 = __expf(s[j][0] - m0);
            const float p01 = __expf(s[j][1] - m0);
            const float p10 = __expf(s[j][2] - m1);
            const float p11 = __expf(s[j][3] - m1);
            ls0 += p00 + p01;
            ls1 += p10 + p11;
            pf[j][0] = pack_half2(p00, p01);
            pf[j][1] = pack_half2(p10, p11);
        }
        ls0 += __shfl_xor_sync(0xffffffffu, ls0, 1);
        ls0 += __shfl_xor_sync(0xffffffffu, ls0, 2);
        ls1 += __shfl_xor_sync(0xffffffffu, ls1, 1);
        ls1 += __shfl_xor_sync(0xffffffffu, ls1, 2);
        l0 = l0 * cf0 + ls0;
        l1 = l1 * cf1 + ls1;

#pragma unroll
        for (int jd = 0; jd < 32; jd++) {
            o[jd][0] *= cf0; o[jd][1] *= cf0;
            o[jd][2] *= cf1; o[jd][3] *= cf1;
        }
#pragma unroll
        for (int kc = 0; kc < 4; kc++) {
            uint32_t a[4] = { pf[2 * kc][0], pf[2 * kc][1],
                              pf[2 * kc + 1][0], pf[2 * kc + 1][1] };
#pragma unroll
            for (int p = 0; p < 16; p++) {
                uint32_t vq[4];
                ldsm_x4(vq, sV + (uint32_t)(p * 16 * VT_LDH + kc * 16) * 2);
                MMA_FP16(o[2 * p],     a, (vq + 0));
                MMA_FP16(o[2 * p + 1], a, (vq + 2));
            }
        }
        __syncthreads();
    }

    const float inv0 = 1.0f / l0, inv1 = 1.0f / l1;
    const size_t r0 = (size_t)(b * SQ + qrow0 + wr + g) * QCOLS + h * HD;
    const size_t r1 = (size_t)(b * SQ + qrow0 + wr + g + 8) * QCOLS + h * HD;
#pragma unroll
    for (int jd = 0; jd < 32; jd++) {
        const int cc = jd * 8 + 2 * tg;
        *(uint32_t*)&O[r0 + cc] = pack_half2(o[jd][0] * inv0, o[jd][1] * inv0);
        *(uint32_t*)&O[r1 + cc] = pack_half2(o[jd][2] * inv1, o[jd][3] * inv1);
    }
}

// ---------------------------------------------------------------------------
// Launch. inputs: hidden_states, attention_mask, position_ids, Wq, Wk, Wv, Wo
// Launch order puts gemm_f16(Q) at index 5 so ncu (-s 5 -c 1) profiles it.
// ---------------------------------------------------------------------------
extern "C" void kernel_launch(void* const* d_in, const int* in_sizes, int n_in,
                              void* d_out, int out_size)
{
    const float* X   = (const float*)d_in[0];
    const int*   pos = (const int*)d_in[2];
    const float* Wq  = (const float*)d_in[3];
    const float* Wk  = (const float*)d_in[4];
    const float* Wv  = (const float*)d_in[5];
    const float* Wo  = (const float*)d_in[6];
    float* out = (float*)d_out;

    float *Qb, *Kb, *Vb;
    __half *Qh, *Kh, *Vth, *Ah, *Xh, *WqT, *WkT, *WvT, *WoT;
    cudaGetSymbolAddress((void**)&Qb,  g_Q);
    cudaGetSymbolAddress((void**)&Kb,  g_K);
    cudaGetSymbolAddress((void**)&Vb,  g_V);
    cudaGetSymbolAddress((void**)&Qh,  g_Qh);
    cudaGetSymbolAddress((void**)&Kh,  g_Kh);
    cudaGetSymbolAddress((void**)&Vth, g_Vt);
    cudaGetSymbolAddress((void**)&Ah,  g_Ah);
    cudaGetSymbolAddress((void**)&Xh,  g_Xh);
    cudaGetSymbolAddress((void**)&WqT, g_WqT);
    cudaGetSymbolAddress((void**)&WkT, g_WkT);
    cudaGetSymbolAddress((void**)&WvT, g_WvT);
    cudaGetSymbolAddress((void**)&WoT, g_WoT);

    cudaFuncSetAttribute(gemm_f16, cudaFuncAttributeMaxDynamicSharedMemorySize,
                         GEMM_SMEM_BYTES);
    cudaFuncSetAttribute(flash16, cudaFuncAttributeMaxDynamicSharedMemorySize,
                         FL_SMEM_BYTES);

    init_invfreq<<<1, 128>>>();                                     // 0
    f2h<<<(ROWS * HID / 4 + 255) / 256, 256>>>(X, Xh, ROWS * HID);  // 1
    wtrans<<<dim3(QCOLS / 32, HID / 32), dim3(32, 8)>>>(Wq, WqT, HID, QCOLS); // 2
    wtrans<<<dim3(KCOLS / 32, HID / 32), dim3(32, 8)>>>(Wk, WkT, HID, KCOLS); // 3
    wtrans<<<dim3(KCOLS / 32, HID / 32), dim3(32, 8)>>>(Wv, WvT, HID, KCOLS); // 4

    // 5: Q projection -- profiled by ncu (-s 5 -c 1)
    gemm_f16<<<dim3(QCOLS / 128, ROWS / 128), 256, GEMM_SMEM_BYTES>>>(
        Xh, WqT, Qb, ROWS, QCOLS, HID);
    gemm_f16<<<dim3(KCOLS / 128, ROWS / 128), 256, GEMM_SMEM_BYTES>>>(
        Xh, WkT, Kb, ROWS, KCOLS, HID);
    gemm_f16<<<dim3(KCOLS / 128, ROWS / 128), 256, GEMM_SMEM_BYTES>>>(
        Xh, WvT, Vb, ROWS, KCOLS, HID);

    rope16<<<(ROWS * NH  * 128 + 255) / 256, 256>>>(Qb, Qh, pos, NH, 0.0625f);
    rope16<<<(ROWS * NKV * 128 + 255) / 256, 256>>>(Kb, Kh, pos, NKV, 1.0f);
    vtrans<<<dim3(SQ / 32, HD / 32, 2 * NKV), dim3(32, 8)>>>(Vb, Vth);

    wtrans<<<dim3(HID / 32, QCOLS / 32), dim3(32, 8)>>>(Wo, WoT, QCOLS, HID);

    flash16<<<dim3(SQ / 64, NH, 2), 128, FL_SMEM_BYTES>>>(Qh, Kh, Vth, Ah);

    gemm_f16<<<dim3(HID / 128, ROWS / 128), 256, GEMM_SMEM_BYTES>>>(
        Ah, WoT, out, ROWS, HID, QCOLS);
}

// round 14
// speedup vs baseline: 15.4052x; 1.0757x over previous
#include <cuda_runtime.h>
#include <cuda_fp16.h>
#include <math.h>
#include <stdint.h>

// ---------------------------------------------------------------------------
// Problem constants: B=2, S=2048, HID=2048, NH=16, NKV=4, HD=256
// ---------------------------------------------------------------------------
#define ROWS      4096
#define HID       2048
#define NH        16
#define NKV       4
#define HD        256
#define SQ        2048
#define QCOLS     (NH * HD)    // 4096
#define KCOLS     (NKV * HD)   // 1024
#define NQKV      (QCOLS + 2 * KCOLS)   // 6144

// Scratch (static device globals -- no allocation anywhere)
__device__ __half g_Qh[(size_t)ROWS * QCOLS];                 // rope'd, scaled, PERMUTED dims
__device__ __half g_Kh[(size_t)ROWS * KCOLS];                 // rope'd, PERMUTED dims
__device__ __half g_Vh[(size_t)ROWS * KCOLS];                 // V fp16 linear
__device__ __half g_Vt[(size_t)(2 * NKV) * HD * SQ];          // [b*kvh][dim][key]
__device__ __half g_Ah[(size_t)ROWS * QCOLS];                 // attention out fp16
__device__ __half g_Xh[(size_t)ROWS * HID];                   // hidden fp16
__device__ __half g_Wqkv[(size_t)NQKV * HID];                 // [N][K]: Q(perm)|K(perm)|V
__device__ __half g_WoT[(size_t)HID * QCOLS];
__device__ float  g_invfreq[128];

// ---------------------------------------------------------------------------
// Helpers
// ---------------------------------------------------------------------------
__device__ __forceinline__ uint32_t pack_half2(float a, float b) {
    uint32_t r;
    asm("cvt.rn.f16x2.f32 %0, %2, %1;" : "=r"(r) : "f"(a), "f"(b));
    return r;
}

__device__ __forceinline__ void cpa16(uint32_t saddr, const void* gaddr) {
    asm volatile("cp.async.cg.shared.global [%0], [%1], 16;"
                 :: "r"(saddr), "l"(gaddr));
}
#define CP_COMMIT() asm volatile("cp.async.commit_group;")
#define CP_WAIT1()  asm volatile("cp.async.wait_group 1;")

__device__ __forceinline__ void ldsm_x4(uint32_t* r, uint32_t saddr) {
    asm volatile("ldmatrix.sync.aligned.m8n8.x4.shared.b16 {%0,%1,%2,%3}, [%4];"
                 : "=r"(r[0]), "=r"(r[1]), "=r"(r[2]), "=r"(r[3])
                 : "r"(saddr));
}

#define MMA_FP16(d, a, b)                                                      \
    asm volatile(                                                              \
        "mma.sync.aligned.m16n8k16.row.col.f32.f16.f16.f32 "                   \
        "{%0,%1,%2,%3},{%4,%5,%6,%7},{%8,%9},{%0,%1,%2,%3};"                   \
        : "+f"((d)[0]), "+f"((d)[1]), "+f"((d)[2]), "+f"((d)[3])               \
        : "r"((a)[0]), "r"((a)[1]), "r"((a)[2]), "r"((a)[3]),                  \
          "r"((b)[0]), "r"((b)[1]))

// ---------------------------------------------------------------------------
// Shared GEMM mainloop (proven R12): 128x128 tile, BK=64, 8 warps,
// 3-slot cp.async ring, 1 sync/iter, stride-72 smem (conflict-free ldmatrix).
// ---------------------------------------------------------------------------
#define GLDK   72
#define GSTG   (128 * GLDK)
#define GBOFF  (3 * GSTG)
#define GEMM_SMEM_BYTES (6 * GSTG * 2)

__device__ __forceinline__ void g_load_stage(
    uint32_t sbase, int slot, const __half* Ab, const __half* Bb,
    int K, int tid, int ko)
{
    const uint32_t ab = sbase + (uint32_t)(slot * GSTG) * 2;
    const uint32_t bb = sbase + (uint32_t)((GBOFF + slot * GSTG)) * 2;
#pragma unroll
    for (int i = 0; i < 4; i++) {
        const int c = tid + i * 256;
        const int row = c >> 3, col8 = c & 7;
        const uint32_t so = (uint32_t)(row * GLDK + col8 * 8) * 2;
        cpa16(ab + so, Ab + (size_t)row * K + ko + col8 * 8);
        cpa16(bb + so, Bb + (size_t)row * K + ko + col8 * 8);
    }
}

#define GEMM_MAINLOOP(A_, Bt_, K_)                                             \
    const uint32_t sbase = (uint32_t)__cvta_generic_to_shared(sh);             \
    const uint32_t a_lm = (uint32_t)((wm + (lane & 15)) * GLDK +               \
                                     (lane >> 4) * 8) * 2;                     \
    const uint32_t b_lm = (uint32_t)((wn + (lane >> 4) * 8 + (lane & 7)) *     \
                                     GLDK + ((lane >> 3) & 1) * 8) * 2;        \
    float acc[4][4][4];                                                        \
    _Pragma("unroll")                                                          \
    for (int mi = 0; mi < 4; mi++)                                             \
        _Pragma("unroll")                                                      \
        for (int ni = 0; ni < 4; ni++)                                         \
            _Pragma("unroll")                                                  \
            for (int e = 0; e < 4; e++) acc[mi][ni][e] = 0.f;                  \
    const __half* Abase = (A_)  + (size_t)row0 * (K_);                         \
    const __half* Bbase = (Bt_) + (size_t)col0 * (K_);                         \
    const int nk = (K_) >> 6;                                                  \
    g_load_stage(sbase, 0, Abase, Bbase, (K_), tid, 0);  CP_COMMIT();          \
    g_load_stage(sbase, 1, Abase, Bbase, (K_), tid, 64); CP_COMMIT();          \
    for (int kt = 0; kt < nk; kt++) {                                          \
        CP_WAIT1();                                                            \
        __syncthreads();                                                       \
        if (kt + 2 < nk)                                                       \
            g_load_stage(sbase, (kt + 2) % 3, Abase, Bbase, (K_), tid,         \
                         (kt + 2) * 64);                                       \
        CP_COMMIT();                                                           \
        const uint32_t sAl = sbase + (uint32_t)((kt % 3) * GSTG) * 2;          \
        const uint32_t sBl = sbase + (uint32_t)((GBOFF + (kt % 3) * GSTG)) * 2;\
        _Pragma("unroll")                                                      \
        for (int kc = 0; kc < 4; kc++) {                                       \
            uint32_t af[4][4], bf[4][2];                                       \
            _Pragma("unroll")                                                  \
            for (int mi = 0; mi < 4; mi++)                                     \
                ldsm_x4(af[mi], sAl + a_lm +                                   \
                        (uint32_t)(mi * 16 * GLDK + kc * 16) * 2);             \
            _Pragma("unroll")                                                  \
            for (int p = 0; p < 2; p++) {                                      \
                uint32_t bq[4];                                                \
                ldsm_x4(bq, sBl + b_lm +                                       \
                        (uint32_t)(p * 16 * GLDK + kc * 16) * 2);              \
                bf[2 * p][0]     = bq[0];                                      \
                bf[2 * p][1]     = bq[1];                                      \
                bf[2 * p + 1][0] = bq[2];                                      \
                bf[2 * p + 1][1] = bq[3];                                      \
            }                                                                  \
            _Pragma("unroll")                                                  \
            for (int mi = 0; mi < 4; mi++)                                     \
                _Pragma("unroll")                                              \
                for (int ni = 0; ni < 4; ni++)                                 \
                    MMA_FP16(acc[mi][ni], af[mi], bf[ni]);                     \
        }                                                                      \
    }

// ---------------------------------------------------------------------------
// Fused QKV projection: C = Xh @ Wqkv^T, N = 6144.
// Epilogue: cols [0,4096) -> rope+scale -> Qh fp16 (permuted dims);
//           cols [4096,5120) -> rope -> Kh fp16; cols [5120,6144) -> Vh fp16.
// Weight columns pre-permuted so (c0,c1) = rope pair (x1, x2).
// ---------------------------------------------------------------------------
__global__ __launch_bounds__(256) void gemm_qkv(
    const __half* __restrict__ A, const __half* __restrict__ Bt,
    const int* __restrict__ pos, __half* __restrict__ Qh,
    __half* __restrict__ Kh, __half* __restrict__ Vh)
{
    extern __shared__ __half sh[];
    const int tid  = threadIdx.x;
    const int wid  = tid >> 5;
    const int lane = tid & 31;
    const int g    = lane >> 2;
    const int tg   = lane & 3;
    const int wm   = (wid & 1) * 64;
    const int wn   = (wid >> 1) * 32;
    const int row0 = blockIdx.y * 128;
    const int col0 = blockIdx.x * 128;

    GEMM_MAINLOOP(A, Bt, HID)

    if (col0 >= QCOLS + KCOLS) {
        // V region: plain fp16 store
#pragma unroll
        for (int mi = 0; mi < 4; mi++) {
#pragma unroll
            for (int ni = 0; ni < 4; ni++) {
                const int r  = row0 + wm + mi * 16 + g;
                const int cc = col0 - QCOLS - KCOLS + wn + ni * 8 + tg * 2;
                *(uint32_t*)&Vh[(size_t)r * KCOLS + cc] =
                    pack_half2(acc[mi][ni][0], acc[mi][ni][1]);
                *(uint32_t*)&Vh[(size_t)(r + 8) * KCOLS + cc] =
                    pack_half2(acc[mi][ni][2], acc[mi][ni][3]);
            }
        }
    } else {
        const bool isQ = (col0 < QCOLS);
        const float scale = isQ ? 0.0625f : 1.0f;
        __half* dst = isQ ? Qh : Kh;
        const int cols = isQ ? QCOLS : KCOLS;
        const int cbase = isQ ? col0 : col0 - QCOLS;
#pragma unroll
        for (int mi = 0; mi < 4; mi++) {
            const int r = row0 + wm + mi * 16 + g;
            const float p0 = (float)pos[r];
            const float p1 = (float)pos[r + 8];
#pragma unroll
            for (int ni = 0; ni < 4; ni++) {
                const int cc = cbase + wn + ni * 8 + tg * 2;
                const int i  = (cc & 255) >> 1;     // rope index within head
                const float invf = g_invfreq[i];
                float s0, c0, s1, c1;
                sincosf(p0 * invf, &s0, &c0);
                sincosf(p1 * invf, &s1, &c1);
                const float x1a = acc[mi][ni][0], x2a = acc[mi][ni][1];
                const float x1b = acc[mi][ni][2], x2b = acc[mi][ni][3];
                *(uint32_t*)&dst[(size_t)r * cols + cc] =
                    pack_half2((x1a * c0 - x2a * s0) * scale,
                               (x2a * c0 + x1a * s0) * scale);
                *(uint32_t*)&dst[(size_t)(r + 8) * cols + cc] =
                    pack_half2((x1b * c1 - x2b * s1) * scale,
                               (x2b * c1 + x1b * s1) * scale);
            }
        }
    }
}

// ---------------------------------------------------------------------------
// Output projection GEMM: fp32 out (final result)
// ---------------------------------------------------------------------------
__global__ __launch_bounds__(256) void gemm_f16(
    const __half* __restrict__ A, const __half* __restrict__ Bt,
    float* __restrict__ C, int M, int N, int K)
{
    extern __shared__ __half sh[];
    const int tid  = threadIdx.x;
    const int wid  = tid >> 5;
    const int lane = tid & 31;
    const int g    = lane >> 2;
    const int tg   = lane & 3;
    const int wm   = (wid & 1) * 64;
    const int wn   = (wid >> 1) * 32;
    const int row0 = blockIdx.y * 128;
    const int col0 = blockIdx.x * 128;

    GEMM_MAINLOOP(A, Bt, K)

#pragma unroll
    for (int mi = 0; mi < 4; mi++) {
#pragma unroll
        for (int ni = 0; ni < 4; ni++) {
            const int r  = row0 + wm + mi * 16 + g;
            const int cc = col0 + wn + ni * 8 + tg * 2;
            *(float2*)&C[(size_t)r * N + cc] =
                make_float2(acc[mi][ni][0], acc[mi][ni][1]);
            *(float2*)&C[(size_t)(r + 8) * N + cc] =
                make_float2(acc[mi][ni][2], acc[mi][ni][3]);
        }
    }
}

// ---------------------------------------------------------------------------
// fp32 -> fp16 (vectorized)
// ---------------------------------------------------------------------------
__global__ void f2h(const float* __restrict__ in, __half* __restrict__ out, int n)
{
    const int i = blockIdx.x * blockDim.x + threadIdx.x;
    if (i * 4 >= n) return;
    const float4 v = ((const float4*)in)[i];
    uint2 h;
    h.x = pack_half2(v.x, v.y);
    h.y = pack_half2(v.z, v.w);
    ((uint2*)out)[i] = h;
}

// ---------------------------------------------------------------------------
// Weight transpose+convert: W[K][N] fp32 -> Wt[N][K] fp16.
// perm != 0: permute output row within each 256-wide head:
//   d < 128 -> 2d ; d >= 128 -> 2(d-128)+1   (rope-pair-adjacent layout)
// ---------------------------------------------------------------------------
__global__ void wtrans(const float* __restrict__ W, __half* __restrict__ Wt,
                       int K, int N, int perm)
{
    __shared__ float tile[32][33];
    const int x = threadIdx.x, y = threadIdx.y;
    const int n0 = blockIdx.x * 32, k0 = blockIdx.y * 32;
#pragma unroll
    for (int j = 0; j < 4; j++)
        tile[y + j * 8][x] = W[(size_t)(k0 + y + j * 8) * N + n0 + x];
    __syncthreads();
#pragma unroll
    for (int j = 0; j < 4; j++) {
        int n = n0 + y + j * 8;
        if (perm) {
            const int d = n & 255;
            n = (n & ~255) | ((d < 128) ? (2 * d) : (2 * (d - 128) + 1));
        }
        Wt[(size_t)n * K + k0 + x] = __float2half_rn(tile[x][y + j * 8]);
    }
}

// ---------------------------------------------------------------------------
// inv_freq table (fp64 exp once)
// ---------------------------------------------------------------------------
__global__ void init_invfreq()
{
    const int i = threadIdx.x;
    g_invfreq[i] = (float)exp(-((double)(2 * i) / 256.0) * log(10000.0));
}

// ---------------------------------------------------------------------------
// V transpose (fp16 in): [b*S][kvh*256+d] -> [b*kvh][d][s]
// ---------------------------------------------------------------------------
__global__ void vtrans(const __half* __restrict__ V, __half* __restrict__ Vt)
{
    __shared__ float tile[32][33];
    const int s0 = blockIdx.x * 32, d0 = blockIdx.y * 32, bk = blockIdx.z;
    const int b = bk >> 2, kvh = bk & 3;
    const int x = threadIdx.x, y = threadIdx.y;
#pragma unroll
    for (int j = 0; j < 4; j++)
        tile[y + j * 8][x] = __half2float(
            V[(size_t)(b * SQ + s0 + y + j * 8) * KCOLS + kvh * HD + d0 + x]);
    __syncthreads();
#pragma unroll
    for (int j = 0; j < 4; j++)
        Vt[((size_t)bk * HD + d0 + y + j * 8) * SQ + s0 + x] =
            __float2half_rn(tile[x][y + j * 8]);
}

// ---------------------------------------------------------------------------
// fp16 tensor-core causal flash attention (proven R11/R12). fp16 out.
// Q/K use the permuted head-dim order (dot products invariant).
// ---------------------------------------------------------------------------
#define QK_LDH 264
#define VT_LDH 72
#define FL_SMEM_BYTES ((2 * 64 * QK_LDH + 256 * VT_LDH) * 2)

__global__ __launch_bounds__(128) void flash16(
    const __half* __restrict__ Q, const __half* __restrict__ K,
    const __half* __restrict__ Vt, __half* __restrict__ O)
{
    extern __shared__ __half sh[];
    __half* Qs = sh;
    __half* Ks = Qs + 64 * QK_LDH;
    __half* Vs = Ks + 64 * QK_LDH;

    const int tid  = threadIdx.x;
    const int lane = tid & 31;
    const int w    = tid >> 5;
    const int g    = lane >> 2;
    const int tg   = lane & 3;
    const int qt   = 31 - blockIdx.x;
    const int h    = blockIdx.y;
    const int b    = blockIdx.z;
    const int kvh  = h >> 2;
    const int qrow0 = qt * 64;
    const int wr   = w * 16;

    const uint32_t q_lm = (uint32_t)((wr + (lane & 15)) * QK_LDH +
                                     (lane >> 4) * 8) * 2;
    const uint32_t k_lm = (uint32_t)(((lane >> 4) * 8 + (lane & 7)) * QK_LDH +
                                     ((lane >> 3) & 1) * 8) * 2;
    const uint32_t v_lm = (uint32_t)(((lane >> 4) * 8 + (lane & 7)) * VT_LDH +
                                     ((lane >> 3) & 1) * 8) * 2;
    const uint32_t sQ = (uint32_t)__cvta_generic_to_shared(Qs) + q_lm;
    const uint32_t sK = (uint32_t)__cvta_generic_to_shared(Ks) + k_lm;
    const uint32_t sV = (uint32_t)__cvta_generic_to_shared(Vs) + v_lm;

    {
        const __half* Qg = Q + (size_t)(b * SQ + qrow0) * QCOLS + h * HD;
#pragma unroll
        for (int it = 0; it < 16; it++) {
            const int idx = tid + it * 128;
            const int r = idx >> 5, c8 = idx & 31;
            *(uint4*)&Qs[r * QK_LDH + c8 * 8] =
                *(const uint4*)&Qg[(size_t)r * QCOLS + c8 * 8];
        }
    }

    float o[32][4];
#pragma unroll
    for (int jd = 0; jd < 32; jd++)
#pragma unroll
        for (int e = 0; e < 4; e++) o[jd][e] = 0.f;
    float m0 = -1e30f, m1 = -1e30f, l0 = 0.f, l1 = 0.f;
    __syncthreads();

    for (int kt = 0; kt <= qt; kt++) {
        {
            const __half* Kg = K + (size_t)(b * SQ + kt * 64) * KCOLS + kvh * HD;
            const __half* Vg = Vt + ((size_t)(b * NKV + kvh) * HD) * SQ + kt * 64;
#pragma unroll
            for (int it = 0; it < 16; it++) {
                const int idx = tid + it * 128;
                const int r = idx >> 5, c8 = idx & 31;
                *(uint4*)&Ks[r * QK_LDH + c8 * 8] =
                    *(const uint4*)&Kg[(size_t)r * KCOLS + c8 * 8];
                const int d = idx >> 3, k8 = idx & 7;
                *(uint4*)&Vs[d * VT_LDH + k8 * 8] =
                    *(const uint4*)&Vg[(size_t)d * SQ + k8 * 8];
            }
        }
        __syncthreads();

        float s[8][4];
#pragma unroll
        for (int j = 0; j < 8; j++)
#pragma unroll
            for (int e = 0; e < 4; e++) s[j][e] = 0.f;

#pragma unroll
        for (int kc = 0; kc < 16; kc++) {
            uint32_t a[4];
            ldsm_x4(a, sQ + (uint32_t)(kc * 16) * 2);
#pragma unroll
            for (int p = 0; p < 4; p++) {
                uint32_t kq[4];
                ldsm_x4(kq, sK + (uint32_t)(p * 16 * QK_LDH + kc * 16) * 2);
                MMA_FP16(s[2 * p],     a, (kq + 0));
                MMA_FP16(s[2 * p + 1], a, (kq + 2));
            }
        }

        if (kt == qt) {
            const int r0 = wr + g, r1 = wr + g + 8;
#pragma unroll
            for (int j = 0; j < 8; j++) {
                const int c0 = j * 8 + 2 * tg, c1 = c0 + 1;
                if (c0 > r0) s[j][0] = -1e30f;
                if (c1 > r0) s[j][1] = -1e30f;
                if (c0 > r1) s[j][2] = -1e30f;
                if (c1 > r1) s[j][3] = -1e30f;
            }
        }

        float tm0 = -1e30f, tm1 = -1e30f;
#pragma unroll
        for (int j = 0; j < 8; j++) {
            tm0 = fmaxf(tm0, fmaxf(s[j][0], s[j][1]));
            tm1 = fmaxf(tm1, fmaxf(s[j][2], s[j][3]));
        }
        tm0 = fmaxf(tm0, __shfl_xor_sync(0xffffffffu, tm0, 1));
        tm0 = fmaxf(tm0, __shfl_xor_sync(0xffffffffu, tm0, 2));
        tm1 = fmaxf(tm1, __shfl_xor_sync(0xffffffffu, tm1, 1));
        tm1 = fmaxf(tm1, __shfl_xor_sync(0xffffffffu, tm1, 2));

        const float mn0 = fmaxf(m0, tm0), mn1 = fmaxf(m1, tm1);
        const float cf0 = __expf(m0 - mn0), cf1 = __expf(m1 - mn1);
        m0 = mn0; m1 = mn1;

        uint32_t pf[8][2];
        float ls0 = 0.f, ls1 = 0.f;
#pragma unroll
        for (int j = 0; j < 8; j++) {
            const float p00 = __expf(s[j][0] - m0);
            const float p01 = __expf(s[j][1] - m0);
            const float p10 = __expf(s[j][2] - m1);
            const float p11 = __expf(s[j][3] - m1);
            ls0 += p00 + p01;
            ls1 += p10 + p11;
            pf[j][0] = pack_half2(p00, p01);
            pf[j][1] = pack_half2(p10, p11);
        }
        ls0 += __shfl_xor_sync(0xffffffffu, ls0, 1);
        ls0 += __shfl_xor_sync(0xffffffffu, ls0, 2);
        ls1 += __shfl_xor_sync(0xffffffffu, ls1, 1);
        ls1 += __shfl_xor_sync(0xffffffffu, ls1, 2);
        l0 = l0 * cf0 + ls0;
        l1 = l1 * cf1 + ls1;

#pragma unroll
        for (int jd = 0; jd < 32; jd++) {
            o[jd][0] *= cf0; o[jd][1] *= cf0;
            o[jd][2] *= cf1; o[jd][3] *= cf1;
        }
#pragma unroll
        for (int kc = 0; kc < 4; kc++) {
            uint32_t a[4] = { pf[2 * kc][0], pf[2 * kc][1],
                              pf[2 * kc + 1][0], pf[2 * kc + 1][1] };
#pragma unroll
            for (int p = 0; p < 16; p++) {
                uint32_t vq[4];
                ldsm_x4(vq, sV + (uint32_t)(p * 16 * VT_LDH + kc * 16) * 2);
                MMA_FP16(o[2 * p],     a, (vq + 0));
                MMA_FP16(o[2 * p + 1], a, (vq + 2));
            }
        }
        __syncthreads();
    }

    const float inv0 = 1.0f / l0, inv1 = 1.0f / l1;
    const size_t r0 = (size_t)(b * SQ + qrow0 + wr + g) * QCOLS + h * HD;
    const size_t r1 = (size_t)(b * SQ + qrow0 + wr + g + 8) * QCOLS + h * HD;
#pragma unroll
    for (int jd = 0; jd < 32; jd++) {
        const int cc = jd * 8 + 2 * tg;
        *(uint32_t*)&O[r0 + cc] = pack_half2(o[jd][0] * inv0, o[jd][1] * inv0);
        *(uint32_t*)&O[r1 + cc] = pack_half2(o[jd][2] * inv1, o[jd][3] * inv1);
    }
}

// ---------------------------------------------------------------------------
// Launch. inputs: hidden_states, attention_mask, position_ids, Wq, Wk, Wv, Wo
// ---------------------------------------------------------------------------
extern "C" void kernel_launch(void* const* d_in, const int* in_sizes, int n_in,
                              void* d_out, int out_size)
{
    const float* X   = (const float*)d_in[0];
    const int*   pos = (const int*)d_in[2];
    const float* Wq  = (const float*)d_in[3];
    const float* Wk  = (const float*)d_in[4];
    const float* Wv  = (const float*)d_in[5];
    const float* Wo  = (const float*)d_in[6];
    float* out = (float*)d_out;

    __half *Qh, *Kh, *Vh, *Vth, *Ah, *Xh, *Wqkv, *WoT;
    cudaGetSymbolAddress((void**)&Qh,   g_Qh);
    cudaGetSymbolAddress((void**)&Kh,   g_Kh);
    cudaGetSymbolAddress((void**)&Vh,   g_Vh);
    cudaGetSymbolAddress((void**)&Vth,  g_Vt);
    cudaGetSymbolAddress((void**)&Ah,   g_Ah);
    cudaGetSymbolAddress((void**)&Xh,   g_Xh);
    cudaGetSymbolAddress((void**)&Wqkv, g_Wqkv);
    cudaGetSymbolAddress((void**)&WoT,  g_WoT);

    cudaFuncSetAttribute(gemm_qkv, cudaFuncAttributeMaxDynamicSharedMemorySize,
                         GEMM_SMEM_BYTES);
    cudaFuncSetAttribute(gemm_f16, cudaFuncAttributeMaxDynamicSharedMemorySize,
                         GEMM_SMEM_BYTES);
    cudaFuncSetAttribute(flash16, cudaFuncAttributeMaxDynamicSharedMemorySize,
                         FL_SMEM_BYTES);

    init_invfreq<<<1, 128>>>();
    f2h<<<(ROWS * HID / 4 + 255) / 256, 256>>>(X, Xh, ROWS * HID);

    // Build fused weight matrix [N=6144][K=2048]: Q (perm) | K (perm) | V
    wtrans<<<dim3(QCOLS / 32, HID / 32), dim3(32, 8)>>>(
        Wq, Wqkv, HID, QCOLS, 1);
    wtrans<<<dim3(KCOLS / 32, HID / 32), dim3(32, 8)>>>(
        Wk, Wqkv + (size_t)QCOLS * HID, HID, KCOLS, 1);
    wtrans<<<dim3(KCOLS / 32, HID / 32), dim3(32, 8)>>>(
        Wv, Wqkv + (size_t)(QCOLS + KCOLS) * HID, HID, KCOLS, 0);
    wtrans<<<dim3(HID / 32, QCOLS / 32), dim3(32, 8)>>>(
        Wo, WoT, QCOLS, HID, 0);

    // Fused QKV projection + RoPE + fp16 conversion (single GEMM, N=6144)
    gemm_qkv<<<dim3(NQKV / 128, ROWS / 128), 256, GEMM_SMEM_BYTES>>>(
        Xh, Wqkv, pos, Qh, Kh, Vh);

    // V -> transposed fp16 [b*kvh][d][s]
    vtrans<<<dim3(SQ / 32, HD / 32, 2 * NKV), dim3(32, 8)>>>(Vh, Vth);

    // fp16 tensor-core causal flash attention -> fp16 output
    flash16<<<dim3(SQ / 64, NH, 2), 128, FL_SMEM_BYTES>>>(Qh, Kh, Vth, Ah);

    // Output projection -> fp32 final output
    gemm_f16<<<dim3(HID / 128, ROWS / 128), 256, GEMM_SMEM_BYTES>>>(
        Ah, WoT, out, ROWS, HID, QCOLS);
}